// round 14
// baseline (speedup 1.0000x reference)
#include <cuda_runtime.h>
#include <cuda_bf16.h>
#include <stdint.h>

#define HID   1024
#define NSEQ  1024
#define DHEAD 64

__device__ float g_q[NSEQ * HID];
__device__ float g_k[NSEQ * HID];
__device__ float g_v[NSEQ * HID];
__device__ float g_pk[2048 * HID];
__device__ float g_pq[2048 * HID];
__device__ float g_ctx[NSEQ * HID];
__device__ float g_part0[NSEQ * HID];
__device__ float g_part1[NSEQ * HID];

__device__ __forceinline__ uint32_t f2bf2(float lo, float hi) {
    uint32_t r;
    asm("cvt.rn.bf16x2.f32 %0, %1, %2;" : "=r"(r) : "f"(hi), "f"(lo));
    return r;
}
__device__ __forceinline__ void mma16(float* c, const uint32_t* a, const uint32_t* b) {
    asm volatile(
        "mma.sync.aligned.m16n8k16.row.col.f32.bf16.bf16.f32 "
        "{%0,%1,%2,%3}, {%4,%5,%6,%7}, {%8,%9}, {%0,%1,%2,%3};\n"
        : "+f"(c[0]), "+f"(c[1]), "+f"(c[2]), "+f"(c[3])
        : "r"(a[0]), "r"(a[1]), "r"(a[2]), "r"(a[3]), "r"(b[0]), "r"(b[1]));
}
__device__ __forceinline__ void ldsm4(uint32_t* r, uint32_t addr) {
    asm volatile("ldmatrix.sync.aligned.m8n8.x4.shared.b16 {%0,%1,%2,%3}, [%4];\n"
        : "=r"(r[0]), "=r"(r[1]), "=r"(r[2]), "=r"(r[3]) : "r"(addr));
}
__device__ __forceinline__ uint32_t smem_u32(const void* p) {
    return (uint32_t)__cvta_generic_to_shared(p);
}

#define ASTRIDE 40

// ===== GEMM core (proven 128x128, BK=32, double-buffer). NKT k-tiles. =====
// bias may be null (raw partial write).
__device__ __forceinline__ void gemm_core(
    const float* __restrict__ A, const float* __restrict__ W,
    const float* __restrict__ bias, float* __restrict__ C,
    int m0, int n0, int koff, int nkt,
    __nv_bfloat16 (*As)[128 * ASTRIDE], __nv_bfloat16 (*Ws)[128 * ASTRIDE])
{
    const int t = threadIdx.x, lane = t & 31, warp = t >> 5;
    const int g = lane >> 2, qd = lane & 3;
    const int wm = warp >> 2, wn = warp & 3;
    const int lr7 = lane & 7;

    const uint32_t aoff = ((uint32_t)((wm * 64 + lr7 + ((lane >> 3) & 1) * 8) * ASTRIDE
                          + (lane >> 4) * 8)) * 2;
    const uint32_t boff = ((uint32_t)((wn * 32 + lr7 + (lane >> 4) * 8) * ASTRIDE
                          + ((lane >> 3) & 1) * 8)) * 2;
    const uint32_t asb = smem_u32(As[0]);
    const uint32_t wsb = smem_u32(Ws[0]);
    const uint32_t bufstep = 128 * ASTRIDE * 2;

    const int lrow = t >> 1, lkoff = (t & 1) * 16;
    const float* Ap = A + (size_t)(m0 + lrow) * HID + koff + lkoff;
    const float* Wp = W + (size_t)(n0 + lrow) * HID + koff + lkoff;

    {
        uint32_t pa[8], pw[8];
#pragma unroll
        for (int f = 0; f < 4; f++) {
            float4 va = *(const float4*)(Ap + f * 4);
            float4 vw = *(const float4*)(Wp + f * 4);
            pa[f*2] = f2bf2(va.x, va.y); pa[f*2+1] = f2bf2(va.z, va.w);
            pw[f*2] = f2bf2(vw.x, vw.y); pw[f*2+1] = f2bf2(vw.z, vw.w);
        }
        uint32_t* da = (uint32_t*)&As[0][lrow * ASTRIDE + lkoff];
        uint32_t* dw = (uint32_t*)&Ws[0][lrow * ASTRIDE + lkoff];
        *(uint4*)da = make_uint4(pa[0], pa[1], pa[2], pa[3]);
        *(uint4*)(da + 4) = make_uint4(pa[4], pa[5], pa[6], pa[7]);
        *(uint4*)dw = make_uint4(pw[0], pw[1], pw[2], pw[3]);
        *(uint4*)(dw + 4) = make_uint4(pw[4], pw[5], pw[6], pw[7]);
    }
    __syncthreads();

    float acc[4][4][4];
#pragma unroll
    for (int i = 0; i < 4; i++)
#pragma unroll
        for (int j = 0; j < 4; j++)
#pragma unroll
            for (int e = 0; e < 4; e++) acc[i][j][e] = 0.0f;

    for (int kt = 0; kt < nkt; kt++) {
        const int cur = kt & 1;
        float4 pa4[4], pw4[4];
        const bool more = (kt + 1 < nkt);
        if (more) {
#pragma unroll
            for (int f = 0; f < 4; f++) {
                pa4[f] = *(const float4*)(Ap + (kt + 1) * 32 + f * 4);
                pw4[f] = *(const float4*)(Wp + (kt + 1) * 32 + f * 4);
            }
        }
        const uint32_t Abase = asb + cur * bufstep + aoff;
        const uint32_t Bbase = wsb + cur * bufstep + boff;
#pragma unroll
        for (int kk = 0; kk < 2; kk++) {
            uint32_t af[4][4], bf[4][2];
#pragma unroll
            for (int tm = 0; tm < 4; tm++)
                ldsm4(af[tm], Abase + tm * 16 * ASTRIDE * 2 + kk * 32);
#pragma unroll
            for (int tnp = 0; tnp < 2; tnp++) {
                uint32_t bb[4];
                ldsm4(bb, Bbase + tnp * 16 * ASTRIDE * 2 + kk * 32);
                bf[2*tnp][0] = bb[0]; bf[2*tnp][1] = bb[1];
                bf[2*tnp+1][0] = bb[2]; bf[2*tnp+1][1] = bb[3];
            }
#pragma unroll
            for (int tm = 0; tm < 4; tm++)
#pragma unroll
                for (int tn = 0; tn < 4; tn++) mma16(acc[tm][tn], af[tm], bf[tn]);
        }
        if (more) {
            const int nx = cur ^ 1;
            uint32_t qa[8], qw[8];
#pragma unroll
            for (int f = 0; f < 4; f++) {
                qa[f*2] = f2bf2(pa4[f].x, pa4[f].y); qa[f*2+1] = f2bf2(pa4[f].z, pa4[f].w);
                qw[f*2] = f2bf2(pw4[f].x, pw4[f].y); qw[f*2+1] = f2bf2(pw4[f].z, pw4[f].w);
            }
            uint32_t* da = (uint32_t*)&As[nx][lrow * ASTRIDE + lkoff];
            uint32_t* dw = (uint32_t*)&Ws[nx][lrow * ASTRIDE + lkoff];
            *(uint4*)da = make_uint4(qa[0], qa[1], qa[2], qa[3]);
            *(uint4*)(da + 4) = make_uint4(qa[4], qa[5], qa[6], qa[7]);
            *(uint4*)dw = make_uint4(qw[0], qw[1], qw[2], qw[3]);
            *(uint4*)(dw + 4) = make_uint4(qw[4], qw[5], qw[6], qw[7]);
            __syncthreads();
        }
    }

#pragma unroll
    for (int tm = 0; tm < 4; tm++)
#pragma unroll
        for (int tn = 0; tn < 4; tn++) {
            const int row = m0 + wm * 64 + tm * 16 + g;
            const int col = n0 + wn * 32 + tn * 8 + 2 * qd;
            float bv0 = 0.0f, bv1 = 0.0f;
            if (bias) { bv0 = bias[col]; bv1 = bias[col + 1]; }
            *(float2*)&C[(size_t)row * HID + col] =
                make_float2(acc[tm][tn][0] + bv0, acc[tm][tn][1] + bv1);
            *(float2*)&C[(size_t)(row + 8) * HID + col] =
                make_float2(acc[tm][tn][2] + bv0, acc[tm][tn][3] + bv1);
        }
}

// ===== merged qkv + pos projections: 448 CTAs in one launch =====
__global__ __launch_bounds__(256)
void gemm_qkvpos(const float* __restrict__ hs, const float* __restrict__ rel,
                 const float* __restrict__ Wq, const float* __restrict__ bq,
                 const float* __restrict__ Wk, const float* __restrict__ bk,
                 const float* __restrict__ Wv, const float* __restrict__ bv,
                 const float* __restrict__ Wpk, const float* __restrict__ bpk,
                 const float* __restrict__ Wpq, const float* __restrict__ bpq)
{
    __shared__ __nv_bfloat16 As[2][128 * ASTRIDE];
    __shared__ __nv_bfloat16 Ws[2][128 * ASTRIDE];

    const int tid = blockIdx.x;
    const float *A, *W, *bias; float* C;
    int m0, n0;
    if (tid < 192) {
        const int z = tid / 64, r = tid % 64;
        A = hs;
        W    = (z == 0) ? Wq : ((z == 1) ? Wk : Wv);
        bias = (z == 0) ? bq : ((z == 1) ? bk : bv);
        C    = (z == 0) ? g_q : ((z == 1) ? g_k : g_v);
        m0 = (r >> 3) * 128; n0 = (r & 7) * 128;
    } else {
        const int u = tid - 192;
        const int z = u >> 7, r = u & 127;
        A = rel;
        W    = (z == 0) ? Wpk : Wpq;
        bias = (z == 0) ? bpk : bpq;
        C    = (z == 0) ? g_pk : g_pq;
        m0 = (r >> 3) * 128; n0 = (r & 7) * 128;
    }
    gemm_core(A, W, bias, C, m0, n0, 0, 32, As, Ws);
}

// ===== Wo split-K: grid (8,8,2); z = k-half; raw partials, no bias =====
__global__ __launch_bounds__(256)
void gemm_wo(const float* __restrict__ Wo)
{
    __shared__ __nv_bfloat16 As[2][128 * ASTRIDE];
    __shared__ __nv_bfloat16 Ws[2][128 * ASTRIDE];
    const int z = blockIdx.z;
    float* C = (z == 0) ? g_part0 : g_part1;
    gemm_core(g_ctx, Wo, nullptr, C,
              blockIdx.y * 128, blockIdx.x * 128, z * 512, 16, As, Ws);
}

#define QSTR 72
#define PSTR 136

// ===== fused attention (unchanged from R11, proven) =====
__global__ __launch_bounds__(256, 1)
void attn_fused()
{
    extern __shared__ char smraw[];
    __nv_bfloat16* qS = (__nv_bfloat16*)smraw;
    __nv_bfloat16* kS = qS + 128 * QSTR;
    __nv_bfloat16* bS = kS + 128 * QSTR;
    float*         Gs = (float*)(bS + 256 * QSTR);
    __nv_bfloat16* Ps = (__nv_bfloat16*)Gs;
    __nv_bfloat16* Vt = (__nv_bfloat16*)(Gs + 128 * 132);
    float*         red = (float*)kS;

    const int h = blockIdx.y, i0 = blockIdx.x * 128;
    const int t = threadIdx.x, lane = t & 31, warp = t >> 5;
    const int g = lane >> 2, qd = lane & 3;
    const int wm = warp >> 2, wn = warp & 3;
    const int lr7 = lane & 7;

    const uint32_t aoffQ = ((uint32_t)((wm*64 + lr7 + ((lane>>3)&1)*8) * QSTR + (lane>>4)*8)) * 2;
    const uint32_t boffQ = ((uint32_t)((wn*32 + lr7 + (lane>>4)*8) * QSTR + ((lane>>3)&1)*8)) * 2;
    const uint32_t aoffP = ((uint32_t)((wm*64 + lr7 + ((lane>>3)&1)*8) * PSTR + (lane>>4)*8)) * 2;
    const uint32_t boffV = ((uint32_t)((wn*16 + lr7 + (lane>>4)*8) * PSTR + ((lane>>3)&1)*8)) * 2;
    const uint32_t qSb = smem_u32(qS), kSb = smem_u32(kS), bSb = smem_u32(bS);
    const uint32_t PsB = smem_u32(Ps), VtB = smem_u32(Vt);

    {
        const int lrow = t >> 1, dh = (t & 1) * 32;
        const float* qp = g_q + (size_t)(i0 + lrow) * HID + h * DHEAD + dh;
        uint32_t u[16];
#pragma unroll
        for (int f = 0; f < 8; f++) {
            float4 a = *(const float4*)(qp + f * 4);
            u[f*2] = f2bf2(a.x, a.y); u[f*2+1] = f2bf2(a.z, a.w);
        }
        uint32_t* d = (uint32_t*)&qS[lrow * QSTR + dh];
#pragma unroll
        for (int f = 0; f < 4; f++)
            *(uint4*)(d + f * 4) = make_uint4(u[f*4], u[f*4+1], u[f*4+2], u[f*4+3]);
    }

    float acc[4][2][4];
#pragma unroll
    for (int i = 0; i < 4; i++)
#pragma unroll
        for (int j = 0; j < 2; j++)
#pragma unroll
            for (int e = 0; e < 4; e++) acc[i][j][e] = 0.0f;
    float rs[4][2];
#pragma unroll
    for (int i = 0; i < 4; i++) { rs[i][0] = 0.0f; rs[i][1] = 0.0f; }

    const int brow = (t < 255) ? t : 254;
    const float inv = 0.07216878364870322992f;

    for (int j0 = 0; j0 < NSEQ; j0 += 128) {
        __syncthreads();
        {
            const int lrow = t >> 1, dh = (t & 1) * 32;
            const float* kp = g_k + (size_t)(j0 + lrow) * HID + h * DHEAD + dh;
            uint32_t u[16];
#pragma unroll
            for (int f = 0; f < 8; f++) {
                float4 a = *(const float4*)(kp + f * 4);
                u[f*2] = f2bf2(a.x, a.y); u[f*2+1] = f2bf2(a.z, a.w);
            }
            uint32_t* d = (uint32_t*)&kS[lrow * QSTR + dh];
#pragma unroll
            for (int f = 0; f < 4; f++)
                *(uint4*)(d + f * 4) = make_uint4(u[f*4], u[f*4+1], u[f*4+2], u[f*4+3]);
        }
        {
            const int vr = t >> 1, dblk = (t & 1) * 32;
            const float* vp = g_v + (size_t)(j0 + vr) * HID + h * DHEAD + dblk;
#pragma unroll
            for (int f = 0; f < 8; f++) {
                float4 a = *(const float4*)(vp + f * 4);
                Vt[(dblk + f*4 + 0) * PSTR + vr] = __float2bfloat16(a.x);
                Vt[(dblk + f*4 + 1) * PSTR + vr] = __float2bfloat16(a.y);
                Vt[(dblk + f*4 + 2) * PSTR + vr] = __float2bfloat16(a.z);
                Vt[(dblk + f*4 + 3) * PSTR + vr] = __float2bfloat16(a.w);
            }
        }
        const int dmin = 1024 + i0 - j0 - 127;
        {
            const float* bp = g_pk + (size_t)(dmin + brow) * HID + h * DHEAD;
            uint32_t ub[32];
#pragma unroll
            for (int f = 0; f < 16; f++) {
                float4 a = *(const float4*)(bp + f * 4);
                ub[f*2] = f2bf2(a.x, a.y); ub[f*2+1] = f2bf2(a.z, a.w);
            }
            uint32_t* db = (uint32_t*)&bS[brow * QSTR];
#pragma unroll
            for (int f = 0; f < 8; f++)
                *(uint4*)(db + f * 4) = make_uint4(ub[f*4], ub[f*4+1], ub[f*4+2], ub[f*4+3]);
        }
        __syncthreads();

        float S[4][4][4];
#pragma unroll
        for (int i = 0; i < 4; i++)
#pragma unroll
            for (int j = 0; j < 4; j++)
#pragma unroll
                for (int e = 0; e < 4; e++) S[i][j][e] = 0.0f;

#pragma unroll
        for (int kk = 0; kk < 4; kk++) {
            uint32_t af[4][4], bf[4][2];
#pragma unroll
            for (int tm = 0; tm < 4; tm++)
                ldsm4(af[tm], qSb + aoffQ + tm * 16 * QSTR * 2 + kk * 32);
#pragma unroll
            for (int tnp = 0; tnp < 2; tnp++) {
                uint32_t bb[4];
                ldsm4(bb, kSb + boffQ + tnp * 16 * QSTR * 2 + kk * 32);
                bf[2*tnp][0] = bb[0]; bf[2*tnp][1] = bb[1];
                bf[2*tnp+1][0] = bb[2]; bf[2*tnp+1][1] = bb[3];
            }
#pragma unroll
            for (int tm = 0; tm < 4; tm++)
#pragma unroll
                for (int tn = 0; tn < 4; tn++) mma16(S[tm][tn], af[tm], bf[tn]);
        }

        for (int pass = 0; pass < 2; pass++) {
            if (pass == 1) {
                const float* bp = g_pq + (size_t)(dmin + brow) * HID + h * DHEAD;
                uint32_t ub[32];
#pragma unroll
                for (int f = 0; f < 16; f++) {
                    float4 a = *(const float4*)(bp + f * 4);
                    ub[f*2] = f2bf2(a.x, a.y); ub[f*2+1] = f2bf2(a.z, a.w);
                }
                uint32_t* db = (uint32_t*)&bS[brow * QSTR];
#pragma unroll
                for (int f = 0; f < 8; f++)
                    *(uint4*)(db + f * 4) = make_uint4(ub[f*4], ub[f*4+1], ub[f*4+2], ub[f*4+3]);
                __syncthreads();
            }
            const uint32_t Xb = (pass == 0) ? qSb : kSb;
            for (int bh = 0; bh < 2; bh++) {
                float Ga[4][4][4];
#pragma unroll
                for (int i = 0; i < 4; i++)
#pragma unroll
                    for (int j = 0; j < 4; j++)
#pragma unroll
                        for (int e = 0; e < 4; e++) Ga[i][j][e] = 0.0f;
#pragma unroll
                for (int kk = 0; kk < 4; kk++) {
                    uint32_t af[4][4], bf[4][2];
#pragma unroll
                    for (int tm = 0; tm < 4; tm++)
                        ldsm4(af[tm], Xb + aoffQ + tm * 16 * QSTR * 2 + kk * 32);
#pragma unroll
                    for (int tnp = 0; tnp < 2; tnp++) {
                        uint32_t bb[4];
                        ldsm4(bb, bSb + boffQ + (bh * 128 + tnp * 16) * QSTR * 2 + kk * 32);
                        bf[2*tnp][0] = bb[0]; bf[2*tnp][1] = bb[1];
                        bf[2*tnp+1][0] = bb[2]; bf[2*tnp+1][1] = bb[3];
                    }
#pragma unroll
                    for (int tm = 0; tm < 4; tm++)
#pragma unroll
                        for (int tn = 0; tn < 4; tn++) mma16(Ga[tm][tn], af[tm], bf[tn]);
                }
#pragma unroll
                for (int tm = 0; tm < 4; tm++)
#pragma unroll
                    for (int tn = 0; tn < 4; tn++) {
                        const int r = wm * 64 + tm * 16 + g;
                        const int c = wn * 32 + tn * 8 + 2 * qd;
                        *(float2*)&Gs[r * 132 + c] = make_float2(Ga[tm][tn][0], Ga[tm][tn][1]);
                        *(float2*)&Gs[(r + 8) * 132 + c] = make_float2(Ga[tm][tn][2], Ga[tm][tn][3]);
                    }
                __syncthreads();
#pragma unroll
                for (int tm = 0; tm < 4; tm++)
#pragma unroll
                    for (int tn = 0; tn < 4; tn++) {
                        const int il = wm * 64 + tm * 16 + g;
                        const int jl = wn * 32 + tn * 8 + 2 * qd;
                        const int b0v = il - jl + 127 - bh * 128;
                        const int bv[4] = {b0v, b0v - 1, b0v + 8, b0v + 7};
                        int rv[4];
                        if (pass == 0) { rv[0] = il; rv[1] = il; rv[2] = il + 8; rv[3] = il + 8; }
                        else           { rv[0] = jl; rv[1] = jl + 1; rv[2] = jl; rv[3] = jl + 1; }
#pragma unroll
                        for (int e = 0; e < 4; e++)
                            if ((unsigned)bv[e] < 128u)
                                S[tm][tn][e] += Gs[rv[e] * 132 + bv[e]];
                    }
                __syncthreads();
            }
        }

#pragma unroll
        for (int tm = 0; tm < 4; tm++) {
            float s0 = 0.0f, s1 = 0.0f;
            const int r = wm * 64 + tm * 16 + g;
            const int c = wn * 32 + 2 * qd;
#pragma unroll
            for (int tn = 0; tn < 4; tn++) {
                float e0 = __expf(S[tm][tn][0] * inv);
                float e1 = __expf(S[tm][tn][1] * inv);
                float e2 = __expf(S[tm][tn][2] * inv);
                float e3 = __expf(S[tm][tn][3] * inv);
                s0 += e0 + e1; s1 += e2 + e3;
                *(uint32_t*)&Ps[r * PSTR + c + tn * 8] = f2bf2(e0, e1);
                *(uint32_t*)&Ps[(r + 8) * PSTR + c + tn * 8] = f2bf2(e2, e3);
            }
            rs[tm][0] += s0; rs[tm][1] += s1;
        }
        __syncthreads();

#pragma unroll
        for (int kk = 0; kk < 8; kk++) {
            uint32_t af[4][4], bf[2][2];
#pragma unroll
            for (int tm = 0; tm < 4; tm++)
                ldsm4(af[tm], PsB + aoffP + tm * 16 * PSTR * 2 + kk * 32);
            {
                uint32_t bb[4];
                ldsm4(bb, VtB + boffV + kk * 32);
                bf[0][0] = bb[0]; bf[0][1] = bb[1];
                bf[1][0] = bb[2]; bf[1][1] = bb[3];
            }
#pragma unroll
            for (int tm = 0; tm < 4; tm++)
#pragma unroll
                for (int tn = 0; tn < 2; tn++) mma16(acc[tm][tn], af[tm], bf[tn]);
        }
    }

    __syncthreads();
#pragma unroll
    for (int tm = 0; tm < 4; tm++) {
        float s0 = rs[tm][0], s1 = rs[tm][1];
        s0 += __shfl_xor_sync(0xffffffffu, s0, 1);
        s0 += __shfl_xor_sync(0xffffffffu, s0, 2);
        s1 += __shfl_xor_sync(0xffffffffu, s1, 1);
        s1 += __shfl_xor_sync(0xffffffffu, s1, 2);
        if (qd == 0) {
            const int r = wm * 64 + tm * 16 + g;
            red[r * 4 + wn] = s0;
            red[(r + 8) * 4 + wn] = s1;
        }
    }
    __syncthreads();
    if (t < 128) {
        float s = red[t * 4] + red[t * 4 + 1] + red[t * 4 + 2] + red[t * 4 + 3];
        red[t * 4] = 1.0f / s;
    }
    __syncthreads();
#pragma unroll
    for (int tm = 0; tm < 4; tm++) {
        const int rl = wm * 64 + tm * 16 + g;
        const float ri0 = red[rl * 4];
        const float ri1 = red[(rl + 8) * 4];
#pragma unroll
        for (int tn = 0; tn < 2; tn++) {
            const int row = i0 + rl;
            const int col = h * DHEAD + wn * 16 + tn * 8 + 2 * qd;
            *(float2*)&g_ctx[(size_t)row * HID + col] =
                make_float2(acc[tm][tn][0] * ri0, acc[tm][tn][1] * ri0);
            *(float2*)&g_ctx[(size_t)(row + 8) * HID + col] =
                make_float2(acc[tm][tn][2] * ri1, acc[tm][tn][3] * ri1);
        }
    }
}

// ===== residual + split-K reduce + bias + LayerNorm =====
__global__ __launch_bounds__(256)
void ln_kernel(const float* __restrict__ hs, const float* __restrict__ bo,
               const float* __restrict__ gg, const float* __restrict__ bb,
               float* __restrict__ out)
{
    const int row = blockIdx.x, t = threadIdx.x;
    __shared__ float red[8];
    float4 p0 = *(const float4*)(g_part0 + (size_t)row * HID + t * 4);
    float4 p1 = *(const float4*)(g_part1 + (size_t)row * HID + t * 4);
    float4 bv = *(const float4*)(bo + t * 4);
    float4 hv = *(const float4*)(hs + (size_t)row * HID + t * 4);
    float x0 = p0.x + p1.x + bv.x + hv.x;
    float x1 = p0.y + p1.y + bv.y + hv.y;
    float x2 = p0.z + p1.z + bv.z + hv.z;
    float x3 = p0.w + p1.w + bv.w + hv.w;
    float s = x0+x1+x2+x3;
#pragma unroll
    for (int o = 16; o > 0; o >>= 1) s += __shfl_xor_sync(0xffffffffu, s, o);
    if ((t & 31) == 0) red[t >> 5] = s;
    __syncthreads();
    float mu = (red[0]+red[1]+red[2]+red[3]+red[4]+red[5]+red[6]+red[7]) * (1.0f/1024.0f);
    float d0 = x0-mu, d1 = x1-mu, d2 = x2-mu, d3 = x3-mu;
    float sq = d0*d0 + d1*d1 + d2*d2 + d3*d3;
#pragma unroll
    for (int o = 16; o > 0; o >>= 1) sq += __shfl_xor_sync(0xffffffffu, sq, o);
    __syncthreads();
    if ((t & 31) == 0) red[t >> 5] = sq;
    __syncthreads();
    float var = (red[0]+red[1]+red[2]+red[3]+red[4]+red[5]+red[6]+red[7]) * (1.0f/1024.0f);
    float rstd = rsqrtf(var + 1e-7f);
    float4 g4 = *(const float4*)(gg + t * 4);
    float4 b4 = *(const float4*)(bb + t * 4);
    *(float4*)(out + (size_t)row * HID + t * 4) =
        make_float4(d0*rstd*g4.x + b4.x, d1*rstd*g4.y + b4.y,
                    d2*rstd*g4.z + b4.z, d3*rstd*g4.w + b4.w);
}

extern "C" void kernel_launch(void* const* d_in, const int* in_sizes, int n_in,
                              void* d_out, int out_size)
{
    const float* hs  = (const float*)d_in[0];
    const float* rel = (const float*)d_in[1];
    const float* Wq  = (const float*)d_in[2];  const float* bq  = (const float*)d_in[3];
    const float* Wk  = (const float*)d_in[4];  const float* bk  = (const float*)d_in[5];
    const float* Wv  = (const float*)d_in[6];  const float* bv  = (const float*)d_in[7];
    const float* Wpk = (const float*)d_in[8];  const float* bpk = (const float*)d_in[9];
    const float* Wpq = (const float*)d_in[10]; const float* bpq = (const float*)d_in[11];
    const float* Wo  = (const float*)d_in[12]; const float* bo  = (const float*)d_in[13];
    const float* lng = (const float*)d_in[14]; const float* lnb = (const float*)d_in[15];

    const int fused_smem = (128 * QSTR + 128 * QSTR + 256 * QSTR) * 2
                         + 128 * 132 * 4 + 64 * PSTR * 2;
    cudaFuncSetAttribute(attn_fused, cudaFuncAttributeMaxDynamicSharedMemorySize, fused_smem);

    gemm_qkvpos<<<448, 256>>>(hs, rel, Wq, bq, Wk, bk, Wv, bv, Wpk, bpk, Wpq, bpq);
    attn_fused<<<dim3(8, 16), 256, fused_smem>>>();
    gemm_wo<<<dim3(8, 8, 2), 256>>>(Wo);
    ln_kernel<<<1024, 256>>>(hs, bo, lng, lnb, (float*)d_out);
}

// round 15
// speedup vs baseline: 1.6009x; 1.6009x over previous
#include <cuda_runtime.h>
#include <cuda_bf16.h>
#include <stdint.h>

#define HID   1024
#define NSEQ  1024
#define DHEAD 64

__device__ float g_q[NSEQ * HID];
__device__ float g_k[NSEQ * HID];
__device__ float g_v[NSEQ * HID];
__device__ float g_pk[2048 * HID];
__device__ float g_pq[2048 * HID];
__device__ float g_ctx[NSEQ * HID];
__device__ float g_part0[NSEQ * HID];
__device__ float g_part1[NSEQ * HID];

__device__ __forceinline__ uint32_t f2bf2(float lo, float hi) {
    uint32_t r;
    asm("cvt.rn.bf16x2.f32 %0, %1, %2;" : "=r"(r) : "f"(hi), "f"(lo));
    return r;
}
__device__ __forceinline__ void mma16(float* c, const uint32_t* a, const uint32_t* b) {
    asm volatile(
        "mma.sync.aligned.m16n8k16.row.col.f32.bf16.bf16.f32 "
        "{%0,%1,%2,%3}, {%4,%5,%6,%7}, {%8,%9}, {%0,%1,%2,%3};\n"
        : "+f"(c[0]), "+f"(c[1]), "+f"(c[2]), "+f"(c[3])
        : "r"(a[0]), "r"(a[1]), "r"(a[2]), "r"(a[3]), "r"(b[0]), "r"(b[1]));
}
__device__ __forceinline__ void ldsm4(uint32_t* r, uint32_t addr) {
    asm volatile("ldmatrix.sync.aligned.m8n8.x4.shared.b16 {%0,%1,%2,%3}, [%4];\n"
        : "=r"(r[0]), "=r"(r[1]), "=r"(r[2]), "=r"(r[3]) : "r"(addr));
}
__device__ __forceinline__ uint32_t smem_u32(const void* p) {
    return (uint32_t)__cvta_generic_to_shared(p);
}

#define ASTRIDE 40

// ============== bf16 NT GEMM (exact R11 proven kernel) ==============
__global__ __launch_bounds__(256)
void gemm_bf16(const float* __restrict__ A,
               const float* __restrict__ W0, const float* __restrict__ b0, float* __restrict__ C0,
               const float* __restrict__ W1, const float* __restrict__ b1, float* __restrict__ C1,
               const float* __restrict__ W2, const float* __restrict__ b2, float* __restrict__ C2)
{
    __shared__ __nv_bfloat16 As[2][128 * ASTRIDE];
    __shared__ __nv_bfloat16 Ws[2][128 * ASTRIDE];

    const int z = blockIdx.z;
    const float* W    = (z == 0) ? W0 : ((z == 1) ? W1 : W2);
    const float* bias = (z == 0) ? b0 : ((z == 1) ? b1 : b2);
    float*       C    = (z == 0) ? C0 : ((z == 1) ? C1 : C2);

    const int m0 = blockIdx.y * 128, n0 = blockIdx.x * 128;
    const int t = threadIdx.x, lane = t & 31, warp = t >> 5;
    const int g = lane >> 2, qd = lane & 3;
    const int wm = warp >> 2, wn = warp & 3;
    const int lr7 = lane & 7;

    const uint32_t aoff = ((uint32_t)((wm * 64 + lr7 + ((lane >> 3) & 1) * 8) * ASTRIDE
                          + (lane >> 4) * 8)) * 2;
    const uint32_t boff = ((uint32_t)((wn * 32 + lr7 + (lane >> 4) * 8) * ASTRIDE
                          + ((lane >> 3) & 1) * 8)) * 2;
    const uint32_t asb = smem_u32(As[0]);
    const uint32_t wsb = smem_u32(Ws[0]);
    const uint32_t bufstep = 128 * ASTRIDE * 2;

    const int lrow = t >> 1, lkoff = (t & 1) * 16;
    const float* Ap = A + (size_t)(m0 + lrow) * HID + lkoff;
    const float* Wp = W + (size_t)(n0 + lrow) * HID + lkoff;

    {
        uint32_t pa[8], pw[8];
#pragma unroll
        for (int f = 0; f < 4; f++) {
            float4 va = *(const float4*)(Ap + f * 4);
            float4 vw = *(const float4*)(Wp + f * 4);
            pa[f*2] = f2bf2(va.x, va.y); pa[f*2+1] = f2bf2(va.z, va.w);
            pw[f*2] = f2bf2(vw.x, vw.y); pw[f*2+1] = f2bf2(vw.z, vw.w);
        }
        uint32_t* da = (uint32_t*)&As[0][lrow * ASTRIDE + lkoff];
        uint32_t* dw = (uint32_t*)&Ws[0][lrow * ASTRIDE + lkoff];
        *(uint4*)da = make_uint4(pa[0], pa[1], pa[2], pa[3]);
        *(uint4*)(da + 4) = make_uint4(pa[4], pa[5], pa[6], pa[7]);
        *(uint4*)dw = make_uint4(pw[0], pw[1], pw[2], pw[3]);
        *(uint4*)(dw + 4) = make_uint4(pw[4], pw[5], pw[6], pw[7]);
    }
    __syncthreads();

    float acc[4][4][4];
#pragma unroll
    for (int i = 0; i < 4; i++)
#pragma unroll
        for (int j = 0; j < 4; j++)
#pragma unroll
            for (int e = 0; e < 4; e++) acc[i][j][e] = 0.0f;

    for (int kt = 0; kt < 32; kt++) {
        const int cur = kt & 1;
        float4 pa4[4], pw4[4];
        const bool more = (kt + 1 < 32);
        if (more) {
#pragma unroll
            for (int f = 0; f < 4; f++) {
                pa4[f] = *(const float4*)(Ap + (kt + 1) * 32 + f * 4);
                pw4[f] = *(const float4*)(Wp + (kt + 1) * 32 + f * 4);
            }
        }
        const uint32_t Abase = asb + cur * bufstep + aoff;
        const uint32_t Bbase = wsb + cur * bufstep + boff;
#pragma unroll
        for (int kk = 0; kk < 2; kk++) {
            uint32_t af[4][4], bf[4][2];
#pragma unroll
            for (int tm = 0; tm < 4; tm++)
                ldsm4(af[tm], Abase + tm * 16 * ASTRIDE * 2 + kk * 32);
#pragma unroll
            for (int tnp = 0; tnp < 2; tnp++) {
                uint32_t bb[4];
                ldsm4(bb, Bbase + tnp * 16 * ASTRIDE * 2 + kk * 32);
                bf[2*tnp][0] = bb[0]; bf[2*tnp][1] = bb[1];
                bf[2*tnp+1][0] = bb[2]; bf[2*tnp+1][1] = bb[3];
            }
#pragma unroll
            for (int tm = 0; tm < 4; tm++)
#pragma unroll
                for (int tn = 0; tn < 4; tn++) mma16(acc[tm][tn], af[tm], bf[tn]);
        }
        if (more) {
            const int nx = cur ^ 1;
            uint32_t qa[8], qw[8];
#pragma unroll
            for (int f = 0; f < 4; f++) {
                qa[f*2] = f2bf2(pa4[f].x, pa4[f].y); qa[f*2+1] = f2bf2(pa4[f].z, pa4[f].w);
                qw[f*2] = f2bf2(pw4[f].x, pw4[f].y); qw[f*2+1] = f2bf2(pw4[f].z, pw4[f].w);
            }
            uint32_t* da = (uint32_t*)&As[nx][lrow * ASTRIDE + lkoff];
            uint32_t* dw = (uint32_t*)&Ws[nx][lrow * ASTRIDE + lkoff];
            *(uint4*)da = make_uint4(qa[0], qa[1], qa[2], qa[3]);
            *(uint4*)(da + 4) = make_uint4(qa[4], qa[5], qa[6], qa[7]);
            *(uint4*)dw = make_uint4(qw[0], qw[1], qw[2], qw[3]);
            *(uint4*)(dw + 4) = make_uint4(qw[4], qw[5], qw[6], qw[7]);
            __syncthreads();
        }
    }

#pragma unroll
    for (int tm = 0; tm < 4; tm++)
#pragma unroll
        for (int tn = 0; tn < 4; tn++) {
            const int row = m0 + wm * 64 + tm * 16 + g;
            const int col = n0 + wn * 32 + tn * 8 + 2 * qd;
            const float bv0 = bias[col], bv1 = bias[col + 1];
            *(float2*)&C[(size_t)row * HID + col] =
                make_float2(acc[tm][tn][0] + bv0, acc[tm][tn][1] + bv1);
            *(float2*)&C[(size_t)(row + 8) * HID + col] =
                make_float2(acc[tm][tn][2] + bv0, acc[tm][tn][3] + bv1);
        }
}

// ===== Wo split-K: same proven body, literal 16 k-tiles, raw partial out =====
__global__ __launch_bounds__(256)
void gemm_wo(const float* __restrict__ Wo)
{
    __shared__ __nv_bfloat16 As[2][128 * ASTRIDE];
    __shared__ __nv_bfloat16 Ws[2][128 * ASTRIDE];

    const int z = blockIdx.z;
    float* C = (z == 0) ? g_part0 : g_part1;
    const int koff = z * 512;

    const int m0 = blockIdx.y * 128, n0 = blockIdx.x * 128;
    const int t = threadIdx.x, lane = t & 31, warp = t >> 5;
    const int g = lane >> 2, qd = lane & 3;
    const int wm = warp >> 2, wn = warp & 3;
    const int lr7 = lane & 7;

    const uint32_t aoff = ((uint32_t)((wm * 64 + lr7 + ((lane >> 3) & 1) * 8) * ASTRIDE
                          + (lane >> 4) * 8)) * 2;
    const uint32_t boff = ((uint32_t)((wn * 32 + lr7 + (lane >> 4) * 8) * ASTRIDE
                          + ((lane >> 3) & 1) * 8)) * 2;
    const uint32_t asb = smem_u32(As[0]);
    const uint32_t wsb = smem_u32(Ws[0]);
    const uint32_t bufstep = 128 * ASTRIDE * 2;

    const int lrow = t >> 1, lkoff = (t & 1) * 16;
    const float* Ap = g_ctx + (size_t)(m0 + lrow) * HID + koff + lkoff;
    const float* Wp = Wo + (size_t)(n0 + lrow) * HID + koff + lkoff;

    {
        uint32_t pa[8], pw[8];
#pragma unroll
        for (int f = 0; f < 4; f++) {
            float4 va = *(const float4*)(Ap + f * 4);
            float4 vw = *(const float4*)(Wp + f * 4);
            pa[f*2] = f2bf2(va.x, va.y); pa[f*2+1] = f2bf2(va.z, va.w);
            pw[f*2] = f2bf2(vw.x, vw.y); pw[f*2+1] = f2bf2(vw.z, vw.w);
        }
        uint32_t* da = (uint32_t*)&As[0][lrow * ASTRIDE + lkoff];
        uint32_t* dw = (uint32_t*)&Ws[0][lrow * ASTRIDE + lkoff];
        *(uint4*)da = make_uint4(pa[0], pa[1], pa[2], pa[3]);
        *(uint4*)(da + 4) = make_uint4(pa[4], pa[5], pa[6], pa[7]);
        *(uint4*)dw = make_uint4(pw[0], pw[1], pw[2], pw[3]);
        *(uint4*)(dw + 4) = make_uint4(pw[4], pw[5], pw[6], pw[7]);
    }
    __syncthreads();

    float acc[4][4][4];
#pragma unroll
    for (int i = 0; i < 4; i++)
#pragma unroll
        for (int j = 0; j < 4; j++)
#pragma unroll
            for (int e = 0; e < 4; e++) acc[i][j][e] = 0.0f;

    for (int kt = 0; kt < 16; kt++) {
        const int cur = kt & 1;
        float4 pa4[4], pw4[4];
        const bool more = (kt + 1 < 16);
        if (more) {
#pragma unroll
            for (int f = 0; f < 4; f++) {
                pa4[f] = *(const float4*)(Ap + (kt + 1) * 32 + f * 4);
                pw4[f] = *(const float4*)(Wp + (kt + 1) * 32 + f * 4);
            }
        }
        const uint32_t Abase = asb + cur * bufstep + aoff;
        const uint32_t Bbase = wsb + cur * bufstep + boff;
#pragma unroll
        for (int kk = 0; kk < 2; kk++) {
            uint32_t af[4][4], bf[4][2];
#pragma unroll
            for (int tm = 0; tm < 4; tm++)
                ldsm4(af[tm], Abase + tm * 16 * ASTRIDE * 2 + kk * 32);
#pragma unroll
            for (int tnp = 0; tnp < 2; tnp++) {
                uint32_t bb[4];
                ldsm4(bb, Bbase + tnp * 16 * ASTRIDE * 2 + kk * 32);
                bf[2*tnp][0] = bb[0]; bf[2*tnp][1] = bb[1];
                bf[2*tnp+1][0] = bb[2]; bf[2*tnp+1][1] = bb[3];
            }
#pragma unroll
            for (int tm = 0; tm < 4; tm++)
#pragma unroll
                for (int tn = 0; tn < 4; tn++) mma16(acc[tm][tn], af[tm], bf[tn]);
        }
        if (more) {
            const int nx = cur ^ 1;
            uint32_t qa[8], qw[8];
#pragma unroll
            for (int f = 0; f < 4; f++) {
                qa[f*2] = f2bf2(pa4[f].x, pa4[f].y); qa[f*2+1] = f2bf2(pa4[f].z, pa4[f].w);
                qw[f*2] = f2bf2(pw4[f].x, pw4[f].y); qw[f*2+1] = f2bf2(pw4[f].z, pw4[f].w);
            }
            uint32_t* da = (uint32_t*)&As[nx][lrow * ASTRIDE + lkoff];
            uint32_t* dw = (uint32_t*)&Ws[nx][lrow * ASTRIDE + lkoff];
            *(uint4*)da = make_uint4(qa[0], qa[1], qa[2], qa[3]);
            *(uint4*)(da + 4) = make_uint4(qa[4], qa[5], qa[6], qa[7]);
            *(uint4*)dw = make_uint4(qw[0], qw[1], qw[2], qw[3]);
            *(uint4*)(dw + 4) = make_uint4(qw[4], qw[5], qw[6], qw[7]);
            __syncthreads();
        }
    }

#pragma unroll
    for (int tm = 0; tm < 4; tm++)
#pragma unroll
        for (int tn = 0; tn < 4; tn++) {
            const int row = m0 + wm * 64 + tm * 16 + g;
            const int col = n0 + wn * 32 + tn * 8 + 2 * qd;
            *(float2*)&C[(size_t)row * HID + col] =
                make_float2(acc[tm][tn][0], acc[tm][tn][1]);
            *(float2*)&C[(size_t)(row + 8) * HID + col] =
                make_float2(acc[tm][tn][2], acc[tm][tn][3]);
        }
}

#define QSTR 72
#define PSTR 136

// ===== fused attention (exact R11 proven kernel) =====
__global__ __launch_bounds__(256, 1)
void attn_fused()
{
    extern __shared__ char smraw[];
    __nv_bfloat16* qS = (__nv_bfloat16*)smraw;
    __nv_bfloat16* kS = qS + 128 * QSTR;
    __nv_bfloat16* bS = kS + 128 * QSTR;
    float*         Gs = (float*)(bS + 256 * QSTR);
    __nv_bfloat16* Ps = (__nv_bfloat16*)Gs;
    __nv_bfloat16* Vt = (__nv_bfloat16*)(Gs + 128 * 132);
    float*         red = (float*)kS;

    const int h = blockIdx.y, i0 = blockIdx.x * 128;
    const int t = threadIdx.x, lane = t & 31, warp = t >> 5;
    const int g = lane >> 2, qd = lane & 3;
    const int wm = warp >> 2, wn = warp & 3;
    const int lr7 = lane & 7;

    const uint32_t aoffQ = ((uint32_t)((wm*64 + lr7 + ((lane>>3)&1)*8) * QSTR + (lane>>4)*8)) * 2;
    const uint32_t boffQ = ((uint32_t)((wn*32 + lr7 + (lane>>4)*8) * QSTR + ((lane>>3)&1)*8)) * 2;
    const uint32_t aoffP = ((uint32_t)((wm*64 + lr7 + ((lane>>3)&1)*8) * PSTR + (lane>>4)*8)) * 2;
    const uint32_t boffV = ((uint32_t)((wn*16 + lr7 + (lane>>4)*8) * PSTR + ((lane>>3)&1)*8)) * 2;
    const uint32_t qSb = smem_u32(qS), kSb = smem_u32(kS), bSb = smem_u32(bS);
    const uint32_t PsB = smem_u32(Ps), VtB = smem_u32(Vt);

    {
        const int lrow = t >> 1, dh = (t & 1) * 32;
        const float* qp = g_q + (size_t)(i0 + lrow) * HID + h * DHEAD + dh;
        uint32_t u[16];
#pragma unroll
        for (int f = 0; f < 8; f++) {
            float4 a = *(const float4*)(qp + f * 4);
            u[f*2] = f2bf2(a.x, a.y); u[f*2+1] = f2bf2(a.z, a.w);
        }
        uint32_t* d = (uint32_t*)&qS[lrow * QSTR + dh];
#pragma unroll
        for (int f = 0; f < 4; f++)
            *(uint4*)(d + f * 4) = make_uint4(u[f*4], u[f*4+1], u[f*4+2], u[f*4+3]);
    }

    float acc[4][2][4];
#pragma unroll
    for (int i = 0; i < 4; i++)
#pragma unroll
        for (int j = 0; j < 2; j++)
#pragma unroll
            for (int e = 0; e < 4; e++) acc[i][j][e] = 0.0f;
    float rs[4][2];
#pragma unroll
    for (int i = 0; i < 4; i++) { rs[i][0] = 0.0f; rs[i][1] = 0.0f; }

    const int brow = (t < 255) ? t : 254;
    const float inv = 0.07216878364870322992f;

    for (int j0 = 0; j0 < NSEQ; j0 += 128) {
        __syncthreads();
        {
            const int lrow = t >> 1, dh = (t & 1) * 32;
            const float* kp = g_k + (size_t)(j0 + lrow) * HID + h * DHEAD + dh;
            uint32_t u[16];
#pragma unroll
            for (int f = 0; f < 8; f++) {
                float4 a = *(const float4*)(kp + f * 4);
                u[f*2] = f2bf2(a.x, a.y); u[f*2+1] = f2bf2(a.z, a.w);
            }
            uint32_t* d = (uint32_t*)&kS[lrow * QSTR + dh];
#pragma unroll
            for (int f = 0; f < 4; f++)
                *(uint4*)(d + f * 4) = make_uint4(u[f*4], u[f*4+1], u[f*4+2], u[f*4+3]);
        }
        {
            const int vr = t >> 1, dblk = (t & 1) * 32;
            const float* vp = g_v + (size_t)(j0 + vr) * HID + h * DHEAD + dblk;
#pragma unroll
            for (int f = 0; f < 8; f++) {
                float4 a = *(const float4*)(vp + f * 4);
                Vt[(dblk + f*4 + 0) * PSTR + vr] = __float2bfloat16(a.x);
                Vt[(dblk + f*4 + 1) * PSTR + vr] = __float2bfloat16(a.y);
                Vt[(dblk + f*4 + 2) * PSTR + vr] = __float2bfloat16(a.z);
                Vt[(dblk + f*4 + 3) * PSTR + vr] = __float2bfloat16(a.w);
            }
        }
        const int dmin = 1024 + i0 - j0 - 127;
        {
            const float* bp = g_pk + (size_t)(dmin + brow) * HID + h * DHEAD;
            uint32_t ub[32];
#pragma unroll
            for (int f = 0; f < 16; f++) {
                float4 a = *(const float4*)(bp + f * 4);
                ub[f*2] = f2bf2(a.x, a.y); ub[f*2+1] = f2bf2(a.z, a.w);
            }
            uint32_t* db = (uint32_t*)&bS[brow * QSTR];
#pragma unroll
            for (int f = 0; f < 8; f++)
                *(uint4*)(db + f * 4) = make_uint4(ub[f*4], ub[f*4+1], ub[f*4+2], ub[f*4+3]);
        }
        __syncthreads();

        float S[4][4][4];
#pragma unroll
        for (int i = 0; i < 4; i++)
#pragma unroll
            for (int j = 0; j < 4; j++)
#pragma unroll
                for (int e = 0; e < 4; e++) S[i][j][e] = 0.0f;

#pragma unroll
        for (int kk = 0; kk < 4; kk++) {
            uint32_t af[4][4], bf[4][2];
#pragma unroll
            for (int tm = 0; tm < 4; tm++)
                ldsm4(af[tm], qSb + aoffQ + tm * 16 * QSTR * 2 + kk * 32);
#pragma unroll
            for (int tnp = 0; tnp < 2; tnp++) {
                uint32_t bb[4];
                ldsm4(bb, kSb + boffQ + tnp * 16 * QSTR * 2 + kk * 32);
                bf[2*tnp][0] = bb[0]; bf[2*tnp][1] = bb[1];
                bf[2*tnp+1][0] = bb[2]; bf[2*tnp+1][1] = bb[3];
            }
#pragma unroll
            for (int tm = 0; tm < 4; tm++)
#pragma unroll
                for (int tn = 0; tn < 4; tn++) mma16(S[tm][tn], af[tm], bf[tn]);
        }

        for (int pass = 0; pass < 2; pass++) {
            if (pass == 1) {
                const float* bp = g_pq + (size_t)(dmin + brow) * HID + h * DHEAD;
                uint32_t ub[32];
#pragma unroll
                for (int f = 0; f < 16; f++) {
                    float4 a = *(const float4*)(bp + f * 4);
                    ub[f*2] = f2bf2(a.x, a.y); ub[f*2+1] = f2bf2(a.z, a.w);
                }
                uint32_t* db = (uint32_t*)&bS[brow * QSTR];
#pragma unroll
                for (int f = 0; f < 8; f++)
                    *(uint4*)(db + f * 4) = make_uint4(ub[f*4], ub[f*4+1], ub[f*4+2], ub[f*4+3]);
                __syncthreads();
            }
            const uint32_t Xb = (pass == 0) ? qSb : kSb;
            for (int bh = 0; bh < 2; bh++) {
                float Ga[4][4][4];
#pragma unroll
                for (int i = 0; i < 4; i++)
#pragma unroll
                    for (int j = 0; j < 4; j++)
#pragma unroll
                        for (int e = 0; e < 4; e++) Ga[i][j][e] = 0.0f;
#pragma unroll
                for (int kk = 0; kk < 4; kk++) {
                    uint32_t af[4][4], bf[4][2];
#pragma unroll
                    for (int tm = 0; tm < 4; tm++)
                        ldsm4(af[tm], Xb + aoffQ + tm * 16 * QSTR * 2 + kk * 32);
#pragma unroll
                    for (int tnp = 0; tnp < 2; tnp++) {
                        uint32_t bb[4];
                        ldsm4(bb, bSb + boffQ + (bh * 128 + tnp * 16) * QSTR * 2 + kk * 32);
                        bf[2*tnp][0] = bb[0]; bf[2*tnp][1] = bb[1];
                        bf[2*tnp+1][0] = bb[2]; bf[2*tnp+1][1] = bb[3];
                    }
#pragma unroll
                    for (int tm = 0; tm < 4; tm++)
#pragma unroll
                        for (int tn = 0; tn < 4; tn++) mma16(Ga[tm][tn], af[tm], bf[tn]);
                }
#pragma unroll
                for (int tm = 0; tm < 4; tm++)
#pragma unroll
                    for (int tn = 0; tn < 4; tn++) {
                        const int r = wm * 64 + tm * 16 + g;
                        const int c = wn * 32 + tn * 8 + 2 * qd;
                        *(float2*)&Gs[r * 132 + c] = make_float2(Ga[tm][tn][0], Ga[tm][tn][1]);
                        *(float2*)&Gs[(r + 8) * 132 + c] = make_float2(Ga[tm][tn][2], Ga[tm][tn][3]);
                    }
                __syncthreads();
#pragma unroll
                for (int tm = 0; tm < 4; tm++)
#pragma unroll
                    for (int tn = 0; tn < 4; tn++) {
                        const int il = wm * 64 + tm * 16 + g;
                        const int jl = wn * 32 + tn * 8 + 2 * qd;
                        const int b0v = il - jl + 127 - bh * 128;
                        const int bv[4] = {b0v, b0v - 1, b0v + 8, b0v + 7};
                        int rv[4];
                        if (pass == 0) { rv[0] = il; rv[1] = il; rv[2] = il + 8; rv[3] = il + 8; }
                        else           { rv[0] = jl; rv[1] = jl + 1; rv[2] = jl; rv[3] = jl + 1; }
#pragma unroll
                        for (int e = 0; e < 4; e++)
                            if ((unsigned)bv[e] < 128u)
                                S[tm][tn][e] += Gs[rv[e] * 132 + bv[e]];
                    }
                __syncthreads();
            }
        }

#pragma unroll
        for (int tm = 0; tm < 4; tm++) {
            float s0 = 0.0f, s1 = 0.0f;
            const int r = wm * 64 + tm * 16 + g;
            const int c = wn * 32 + 2 * qd;
#pragma unroll
            for (int tn = 0; tn < 4; tn++) {
                float e0 = __expf(S[tm][tn][0] * inv);
                float e1 = __expf(S[tm][tn][1] * inv);
                float e2 = __expf(S[tm][tn][2] * inv);
                float e3 = __expf(S[tm][tn][3] * inv);
                s0 += e0 + e1; s1 += e2 + e3;
                *(uint32_t*)&Ps[r * PSTR + c + tn * 8] = f2bf2(e0, e1);
                *(uint32_t*)&Ps[(r + 8) * PSTR + c + tn * 8] = f2bf2(e2, e3);
            }
            rs[tm][0] += s0; rs[tm][1] += s1;
        }
        __syncthreads();

#pragma unroll
        for (int kk = 0; kk < 8; kk++) {
            uint32_t af[4][4], bf[2][2];
#pragma unroll
            for (int tm = 0; tm < 4; tm++)
                ldsm4(af[tm], PsB + aoffP + tm * 16 * PSTR * 2 + kk * 32);
            {
                uint32_t bb[4];
                ldsm4(bb, VtB + boffV + kk * 32);
                bf[0][0] = bb[0]; bf[0][1] = bb[1];
                bf[1][0] = bb[2]; bf[1][1] = bb[3];
            }
#pragma unroll
            for (int tm = 0; tm < 4; tm++)
#pragma unroll
                for (int tn = 0; tn < 2; tn++) mma16(acc[tm][tn], af[tm], bf[tn]);
        }
    }

    __syncthreads();
#pragma unroll
    for (int tm = 0; tm < 4; tm++) {
        float s0 = rs[tm][0], s1 = rs[tm][1];
        s0 += __shfl_xor_sync(0xffffffffu, s0, 1);
        s0 += __shfl_xor_sync(0xffffffffu, s0, 2);
        s1 += __shfl_xor_sync(0xffffffffu, s1, 1);
        s1 += __shfl_xor_sync(0xffffffffu, s1, 2);
        if (qd == 0) {
            const int r = wm * 64 + tm * 16 + g;
            red[r * 4 + wn] = s0;
            red[(r + 8) * 4 + wn] = s1;
        }
    }
    __syncthreads();
    if (t < 128) {
        float s = red[t * 4] + red[t * 4 + 1] + red[t * 4 + 2] + red[t * 4 + 3];
        red[t * 4] = 1.0f / s;
    }
    __syncthreads();
#pragma unroll
    for (int tm = 0; tm < 4; tm++) {
        const int rl = wm * 64 + tm * 16 + g;
        const float ri0 = red[rl * 4];
        const float ri1 = red[(rl + 8) * 4];
#pragma unroll
        for (int tn = 0; tn < 2; tn++) {
            const int row = i0 + rl;
            const int col = h * DHEAD + wn * 16 + tn * 8 + 2 * qd;
            *(float2*)&g_ctx[(size_t)row * HID + col] =
                make_float2(acc[tm][tn][0] * ri0, acc[tm][tn][1] * ri0);
            *(float2*)&g_ctx[(size_t)(row + 8) * HID + col] =
                make_float2(acc[tm][tn][2] * ri1, acc[tm][tn][3] * ri1);
        }
    }
}

// ===== residual + split-K reduce + bias + LayerNorm =====
__global__ __launch_bounds__(256)
void ln_kernel(const float* __restrict__ hs, const float* __restrict__ bo,
               const float* __restrict__ gg, const float* __restrict__ bb,
               float* __restrict__ out)
{
    const int row = blockIdx.x, t = threadIdx.x;
    __shared__ float red[8];
    float4 p0 = *(const float4*)(g_part0 + (size_t)row * HID + t * 4);
    float4 p1 = *(const float4*)(g_part1 + (size_t)row * HID + t * 4);
    float4 bv = *(const float4*)(bo + t * 4);
    float4 hv = *(const float4*)(hs + (size_t)row * HID + t * 4);
    float x0 = p0.x + p1.x + bv.x + hv.x;
    float x1 = p0.y + p1.y + bv.y + hv.y;
    float x2 = p0.z + p1.z + bv.z + hv.z;
    float x3 = p0.w + p1.w + bv.w + hv.w;
    float s = x0+x1+x2+x3;
#pragma unroll
    for (int o = 16; o > 0; o >>= 1) s += __shfl_xor_sync(0xffffffffu, s, o);
    if ((t & 31) == 0) red[t >> 5] = s;
    __syncthreads();
    float mu = (red[0]+red[1]+red[2]+red[3]+red[4]+red[5]+red[6]+red[7]) * (1.0f/1024.0f);
    float d0 = x0-mu, d1 = x1-mu, d2 = x2-mu, d3 = x3-mu;
    float sq = d0*d0 + d1*d1 + d2*d2 + d3*d3;
#pragma unroll
    for (int o = 16; o > 0; o >>= 1) sq += __shfl_xor_sync(0xffffffffu, sq, o);
    __syncthreads();
    if ((t & 31) == 0) red[t >> 5] = sq;
    __syncthreads();
    float var = (red[0]+red[1]+red[2]+red[3]+red[4]+red[5]+red[6]+red[7]) * (1.0f/1024.0f);
    float rstd = rsqrtf(var + 1e-7f);
    float4 g4 = *(const float4*)(gg + t * 4);
    float4 b4 = *(const float4*)(bb + t * 4);
    *(float4*)(out + (size_t)row * HID + t * 4) =
        make_float4(d0*rstd*g4.x + b4.x, d1*rstd*g4.y + b4.y,
                    d2*rstd*g4.z + b4.z, d3*rstd*g4.w + b4.w);
}

extern "C" void kernel_launch(void* const* d_in, const int* in_sizes, int n_in,
                              void* d_out, int out_size)
{
    const float* hs  = (const float*)d_in[0];
    const float* rel = (const float*)d_in[1];
    const float* Wq  = (const float*)d_in[2];  const float* bq  = (const float*)d_in[3];
    const float* Wk  = (const float*)d_in[4];  const float* bk  = (const float*)d_in[5];
    const float* Wv  = (const float*)d_in[6];  const float* bv  = (const float*)d_in[7];
    const float* Wpk = (const float*)d_in[8];  const float* bpk = (const float*)d_in[9];
    const float* Wpq = (const float*)d_in[10]; const float* bpq = (const float*)d_in[11];
    const float* Wo  = (const float*)d_in[12]; const float* bo  = (const float*)d_in[13];
    const float* lng = (const float*)d_in[14]; const float* lnb = (const float*)d_in[15];

    float *q_, *k_, *v_, *pk_, *pq_;
    cudaGetSymbolAddress((void**)&q_, g_q);
    cudaGetSymbolAddress((void**)&k_, g_k);
    cudaGetSymbolAddress((void**)&v_, g_v);
    cudaGetSymbolAddress((void**)&pk_, g_pk);
    cudaGetSymbolAddress((void**)&pq_, g_pq);

    const int fused_smem = (128 * QSTR + 128 * QSTR + 256 * QSTR) * 2
                         + 128 * 132 * 4 + 64 * PSTR * 2;
    cudaFuncSetAttribute(attn_fused, cudaFuncAttributeMaxDynamicSharedMemorySize, fused_smem);

    gemm_bf16<<<dim3(8, 8, 3), 256>>>(hs, Wq, bq, q_, Wk, bk, k_, Wv, bv, v_);
    gemm_bf16<<<dim3(8, 16, 2), 256>>>(rel, Wpk, bpk, pk_, Wpq, bpq, pq_, Wpq, bpq, pq_);
    attn_fused<<<dim3(8, 16), 256, fused_smem>>>();
    gemm_wo<<<dim3(8, 8, 2), 256>>>(Wo);
    ln_kernel<<<1024, 256>>>(hs, bo, lng, lnb, (float*)d_out);
}

// round 16
// speedup vs baseline: 2.3016x; 1.4378x over previous
#include <cuda_runtime.h>
#include <cuda_bf16.h>
#include <stdint.h>

#define HID   1024
#define NSEQ  1024
#define DHEAD 64

typedef __nv_bfloat16 bf;

__device__ bf g_hsb[NSEQ * HID];
__device__ bf g_relb[2048 * HID];
__device__ bf g_Wqb[HID * HID];
__device__ bf g_Wkb[HID * HID];
__device__ bf g_Wvb[HID * HID];
__device__ bf g_Wpkb[HID * HID];
__device__ bf g_Wpqb[HID * HID];
__device__ bf g_Wob[HID * HID];
__device__ bf g_q[NSEQ * HID];
__device__ bf g_k[NSEQ * HID];
__device__ bf g_v[NSEQ * HID];
__device__ bf g_pk[2048 * HID];
__device__ bf g_pq[2048 * HID];
__device__ bf g_ctx[NSEQ * HID];
__device__ float g_part0[NSEQ * HID];
__device__ float g_part1[NSEQ * HID];

__device__ __forceinline__ uint32_t f2bf2(float lo, float hi) {
    uint32_t r;
    asm("cvt.rn.bf16x2.f32 %0, %1, %2;" : "=r"(r) : "f"(hi), "f"(lo));
    return r;
}
__device__ __forceinline__ void mma16(float* c, const uint32_t* a, const uint32_t* b) {
    asm volatile(
        "mma.sync.aligned.m16n8k16.row.col.f32.bf16.bf16.f32 "
        "{%0,%1,%2,%3}, {%4,%5,%6,%7}, {%8,%9}, {%0,%1,%2,%3};\n"
        : "+f"(c[0]), "+f"(c[1]), "+f"(c[2]), "+f"(c[3])
        : "r"(a[0]), "r"(a[1]), "r"(a[2]), "r"(a[3]), "r"(b[0]), "r"(b[1]));
}
__device__ __forceinline__ void ldsm4(uint32_t* r, uint32_t addr) {
    asm volatile("ldmatrix.sync.aligned.m8n8.x4.shared.b16 {%0,%1,%2,%3}, [%4];\n"
        : "=r"(r[0]), "=r"(r[1]), "=r"(r[2]), "=r"(r[3]) : "r"(addr));
}
__device__ __forceinline__ uint32_t smem_u32(const void* p) {
    return (uint32_t)__cvta_generic_to_shared(p);
}
__device__ __forceinline__ void cpa16(uint32_t dst, const void* src) {
    asm volatile("cp.async.cg.shared.global [%0], [%1], 16;\n" :: "r"(dst), "l"(src));
}
__device__ __forceinline__ void cpa_commit() {
    asm volatile("cp.async.commit_group;\n" ::: "memory");
}
__device__ __forceinline__ void cpa_wait0() {
    asm volatile("cp.async.wait_group 0;\n" ::: "memory");
}

// ===== prep: fp32 -> bf16 for hs, rel, 6 weights (1M elems per y-slice) =====
__global__ __launch_bounds__(256)
void conv_bf16(const float* __restrict__ hs, const float* __restrict__ rel,
               const float* __restrict__ Wq, const float* __restrict__ Wk,
               const float* __restrict__ Wv, const float* __restrict__ Wpk,
               const float* __restrict__ Wpq, const float* __restrict__ Wo)
{
    const int y = blockIdx.y;
    const float* src; bf* dst;
    switch (y) {
        case 0: src = hs;            dst = g_hsb;            break;
        case 1: src = rel;           dst = g_relb;           break;
        case 2: src = rel + 1048576; dst = g_relb + 1048576; break;
        case 3: src = Wq;            dst = g_Wqb;            break;
        case 4: src = Wk;            dst = g_Wkb;            break;
        case 5: src = Wv;            dst = g_Wvb;            break;
        case 6: src = Wpk;           dst = g_Wpkb;           break;
        case 7: src = Wpq;           dst = g_Wpqb;           break;
        default: src = Wo;           dst = g_Wob;            break;
    }
    const int idx = (blockIdx.x * 256 + threadIdx.x) * 8;
    float4 a = *(const float4*)(src + idx);
    float4 b = *(const float4*)(src + idx + 4);
    *(uint4*)(dst + idx) = make_uint4(f2bf2(a.x, a.y), f2bf2(a.z, a.w),
                                      f2bf2(b.x, b.y), f2bf2(b.z, b.w));
}

#define ASTRIDE 40

// ===== bf16-in GEMM w/ cp.async staging: C[m][n] = A@W^T + bias, bf16 out ====
__global__ __launch_bounds__(256)
void gemm_proj(const bf* __restrict__ A,
               const bf* __restrict__ W0, const float* __restrict__ b0, bf* __restrict__ C0,
               const bf* __restrict__ W1, const float* __restrict__ b1, bf* __restrict__ C1,
               const bf* __restrict__ W2, const float* __restrict__ b2, bf* __restrict__ C2)
{
    __shared__ bf As[2][128 * ASTRIDE];
    __shared__ bf Ws[2][128 * ASTRIDE];

    const int z = blockIdx.z;
    const bf*    W    = (z == 0) ? W0 : ((z == 1) ? W1 : W2);
    const float* bias = (z == 0) ? b0 : ((z == 1) ? b1 : b2);
    bf*          C    = (z == 0) ? C0 : ((z == 1) ? C1 : C2);

    const int m0 = blockIdx.y * 128, n0 = blockIdx.x * 128;
    const int t = threadIdx.x, lane = t & 31, warp = t >> 5;
    const int g = lane >> 2, qd = lane & 3;
    const int wm = warp >> 2, wn = warp & 3;
    const int lr7 = lane & 7;

    const uint32_t aoff = ((uint32_t)((wm * 64 + lr7 + ((lane >> 3) & 1) * 8) * ASTRIDE
                          + (lane >> 4) * 8)) * 2;
    const uint32_t boff = ((uint32_t)((wn * 32 + lr7 + (lane >> 4) * 8) * ASTRIDE
                          + ((lane >> 3) & 1) * 8)) * 2;
    const uint32_t asb = smem_u32(As[0]);
    const uint32_t wsb = smem_u32(Ws[0]);
    const uint32_t bufstep = 128 * ASTRIDE * 2;

    const int lrow = t >> 1, lk = (t & 1) * 16;
    const bf* Ap = A + (size_t)(m0 + lrow) * HID + lk;
    const bf* Wp = W + (size_t)(n0 + lrow) * HID + lk;
    const uint32_t dA = asb + (uint32_t)(lrow * ASTRIDE + lk) * 2;
    const uint32_t dW = wsb + (uint32_t)(lrow * ASTRIDE + lk) * 2;

    cpa16(dA, Ap);       cpa16(dA + 16, Ap + 8);
    cpa16(dW, Wp);       cpa16(dW + 16, Wp + 8);
    cpa_commit(); cpa_wait0();
    __syncthreads();

    float acc[4][4][4];
#pragma unroll
    for (int i = 0; i < 4; i++)
#pragma unroll
        for (int j = 0; j < 4; j++)
#pragma unroll
            for (int e = 0; e < 4; e++) acc[i][j][e] = 0.0f;

    for (int kt = 0; kt < 32; kt++) {
        const int cur = kt & 1;
        const bool more = (kt + 1 < 32);
        if (more) {
            const int nx = cur ^ 1;
            cpa16(dA + nx * bufstep, Ap + (kt + 1) * 32);
            cpa16(dA + nx * bufstep + 16, Ap + (kt + 1) * 32 + 8);
            cpa16(dW + nx * bufstep, Wp + (kt + 1) * 32);
            cpa16(dW + nx * bufstep + 16, Wp + (kt + 1) * 32 + 8);
            cpa_commit();
        }
        const uint32_t Abase = asb + cur * bufstep + aoff;
        const uint32_t Bbase = wsb + cur * bufstep + boff;
#pragma unroll
        for (int kk = 0; kk < 2; kk++) {
            uint32_t af[4][4], bf2[4][2];
#pragma unroll
            for (int tm = 0; tm < 4; tm++)
                ldsm4(af[tm], Abase + tm * 16 * ASTRIDE * 2 + kk * 32);
#pragma unroll
            for (int tnp = 0; tnp < 2; tnp++) {
                uint32_t bb[4];
                ldsm4(bb, Bbase + tnp * 16 * ASTRIDE * 2 + kk * 32);
                bf2[2*tnp][0] = bb[0]; bf2[2*tnp][1] = bb[1];
                bf2[2*tnp+1][0] = bb[2]; bf2[2*tnp+1][1] = bb[3];
            }
#pragma unroll
            for (int tm = 0; tm < 4; tm++)
#pragma unroll
                for (int tn = 0; tn < 4; tn++) mma16(acc[tm][tn], af[tm], bf2[tn]);
        }
        if (more) {
            cpa_wait0();
            __syncthreads();
        }
    }

#pragma unroll
    for (int tm = 0; tm < 4; tm++)
#pragma unroll
        for (int tn = 0; tn < 4; tn++) {
            const int row = m0 + wm * 64 + tm * 16 + g;
            const int col = n0 + wn * 32 + tn * 8 + 2 * qd;
            const float bv0 = bias[col], bv1 = bias[col + 1];
            *(uint32_t*)&C[(size_t)row * HID + col] =
                f2bf2(acc[tm][tn][0] + bv0, acc[tm][tn][1] + bv1);
            *(uint32_t*)&C[(size_t)(row + 8) * HID + col] =
                f2bf2(acc[tm][tn][2] + bv0, acc[tm][tn][3] + bv1);
        }
}

// ===== Wo split-K (bf16 in via cp.async, fp32 partial out) =====
__global__ __launch_bounds__(256)
void gemm_wo()
{
    __shared__ bf As[2][128 * ASTRIDE];
    __shared__ bf Ws[2][128 * ASTRIDE];

    const int z = blockIdx.z;
    float* C = (z == 0) ? g_part0 : g_part1;
    const int koff = z * 512;

    const int m0 = blockIdx.y * 128, n0 = blockIdx.x * 128;
    const int t = threadIdx.x, lane = t & 31, warp = t >> 5;
    const int g = lane >> 2, qd = lane & 3;
    const int wm = warp >> 2, wn = warp & 3;
    const int lr7 = lane & 7;

    const uint32_t aoff = ((uint32_t)((wm * 64 + lr7 + ((lane >> 3) & 1) * 8) * ASTRIDE
                          + (lane >> 4) * 8)) * 2;
    const uint32_t boff = ((uint32_t)((wn * 32 + lr7 + (lane >> 4) * 8) * ASTRIDE
                          + ((lane >> 3) & 1) * 8)) * 2;
    const uint32_t asb = smem_u32(As[0]);
    const uint32_t wsb = smem_u32(Ws[0]);
    const uint32_t bufstep = 128 * ASTRIDE * 2;

    const int lrow = t >> 1, lk = (t & 1) * 16;
    const bf* Ap = g_ctx + (size_t)(m0 + lrow) * HID + koff + lk;
    const bf* Wp = g_Wob + (size_t)(n0 + lrow) * HID + koff + lk;
    const uint32_t dA = asb + (uint32_t)(lrow * ASTRIDE + lk) * 2;
    const uint32_t dW = wsb + (uint32_t)(lrow * ASTRIDE + lk) * 2;

    cpa16(dA, Ap);       cpa16(dA + 16, Ap + 8);
    cpa16(dW, Wp);       cpa16(dW + 16, Wp + 8);
    cpa_commit(); cpa_wait0();
    __syncthreads();

    float acc[4][4][4];
#pragma unroll
    for (int i = 0; i < 4; i++)
#pragma unroll
        for (int j = 0; j < 4; j++)
#pragma unroll
            for (int e = 0; e < 4; e++) acc[i][j][e] = 0.0f;

    for (int kt = 0; kt < 16; kt++) {
        const int cur = kt & 1;
        const bool more = (kt + 1 < 16);
        if (more) {
            const int nx = cur ^ 1;
            cpa16(dA + nx * bufstep, Ap + (kt + 1) * 32);
            cpa16(dA + nx * bufstep + 16, Ap + (kt + 1) * 32 + 8);
            cpa16(dW + nx * bufstep, Wp + (kt + 1) * 32);
            cpa16(dW + nx * bufstep + 16, Wp + (kt + 1) * 32 + 8);
            cpa_commit();
        }
        const uint32_t Abase = asb + cur * bufstep + aoff;
        const uint32_t Bbase = wsb + cur * bufstep + boff;
#pragma unroll
        for (int kk = 0; kk < 2; kk++) {
            uint32_t af[4][4], bf2[4][2];
#pragma unroll
            for (int tm = 0; tm < 4; tm++)
                ldsm4(af[tm], Abase + tm * 16 * ASTRIDE * 2 + kk * 32);
#pragma unroll
            for (int tnp = 0; tnp < 2; tnp++) {
                uint32_t bb[4];
                ldsm4(bb, Bbase + tnp * 16 * ASTRIDE * 2 + kk * 32);
                bf2[2*tnp][0] = bb[0]; bf2[2*tnp][1] = bb[1];
                bf2[2*tnp+1][0] = bb[2]; bf2[2*tnp+1][1] = bb[3];
            }
#pragma unroll
            for (int tm = 0; tm < 4; tm++)
#pragma unroll
                for (int tn = 0; tn < 4; tn++) mma16(acc[tm][tn], af[tm], bf2[tn]);
        }
        if (more) {
            cpa_wait0();
            __syncthreads();
        }
    }

#pragma unroll
    for (int tm = 0; tm < 4; tm++)
#pragma unroll
        for (int tn = 0; tn < 4; tn++) {
            const int row = m0 + wm * 64 + tm * 16 + g;
            const int col = n0 + wn * 32 + tn * 8 + 2 * qd;
            *(float2*)&C[(size_t)row * HID + col] =
                make_float2(acc[tm][tn][0], acc[tm][tn][1]);
            *(float2*)&C[(size_t)(row + 8) * HID + col] =
                make_float2(acc[tm][tn][2], acc[tm][tn][3]);
        }
}

#define QSTR 72
#define PSTR 136

// ===== fused attention (R11 structure; bf16 input staging = raw copies) =====
__global__ __launch_bounds__(256, 1)
void attn_fused()
{
    extern __shared__ char smraw[];
    bf*    qS = (bf*)smraw;
    bf*    kS = qS + 128 * QSTR;
    bf*    bS = kS + 128 * QSTR;
    float* Gs = (float*)(bS + 256 * QSTR);
    bf*    Ps = (bf*)Gs;
    bf*    Vt = (bf*)(Gs + 128 * 132);
    float* red = (float*)kS;

    const int h = blockIdx.y, i0 = blockIdx.x * 128;
    const int t = threadIdx.x, lane = t & 31, warp = t >> 5;
    const int g = lane >> 2, qd = lane & 3;
    const int wm = warp >> 2, wn = warp & 3;
    const int lr7 = lane & 7;

    const uint32_t aoffQ = ((uint32_t)((wm*64 + lr7 + ((lane>>3)&1)*8) * QSTR + (lane>>4)*8)) * 2;
    const uint32_t boffQ = ((uint32_t)((wn*32 + lr7 + (lane>>4)*8) * QSTR + ((lane>>3)&1)*8)) * 2;
    const uint32_t aoffP = ((uint32_t)((wm*64 + lr7 + ((lane>>3)&1)*8) * PSTR + (lane>>4)*8)) * 2;
    const uint32_t boffV = ((uint32_t)((wn*16 + lr7 + (lane>>4)*8) * PSTR + ((lane>>3)&1)*8)) * 2;
    const uint32_t qSb = smem_u32(qS), kSb = smem_u32(kS), bSb = smem_u32(bS);
    const uint32_t PsB = smem_u32(Ps), VtB = smem_u32(Vt);

    // stage qS once: raw bf16 copy
    {
        const int lrow = t >> 1, dh = (t & 1) * 32;
        const bf* qp = g_q + (size_t)(i0 + lrow) * HID + h * DHEAD + dh;
        uint4 u0 = *(const uint4*)qp;
        uint4 u1 = *(const uint4*)(qp + 8);
        uint4 u2 = *(const uint4*)(qp + 16);
        uint4 u3 = *(const uint4*)(qp + 24);
        bf* d = &qS[lrow * QSTR + dh];
        *(uint4*)d = u0; *(uint4*)(d + 8) = u1;
        *(uint4*)(d + 16) = u2; *(uint4*)(d + 24) = u3;
    }

    float acc[4][2][4];
#pragma unroll
    for (int i = 0; i < 4; i++)
#pragma unroll
        for (int j = 0; j < 2; j++)
#pragma unroll
            for (int e = 0; e < 4; e++) acc[i][j][e] = 0.0f;
    float rs[4][2];
#pragma unroll
    for (int i = 0; i < 4; i++) { rs[i][0] = 0.0f; rs[i][1] = 0.0f; }

    const int brow = (t < 255) ? t : 254;
    const float inv = 0.07216878364870322992f;

    for (int j0 = 0; j0 < NSEQ; j0 += 128) {
        __syncthreads();
        // stage kS (raw copy)
        {
            const int lrow = t >> 1, dh = (t & 1) * 32;
            const bf* kp = g_k + (size_t)(j0 + lrow) * HID + h * DHEAD + dh;
            uint4 u0 = *(const uint4*)kp;
            uint4 u1 = *(const uint4*)(kp + 8);
            uint4 u2 = *(const uint4*)(kp + 16);
            uint4 u3 = *(const uint4*)(kp + 24);
            bf* d = &kS[lrow * QSTR + dh];
            *(uint4*)d = u0; *(uint4*)(d + 8) = u1;
            *(uint4*)(d + 16) = u2; *(uint4*)(d + 24) = u3;
        }
        // stage Vt[d][j] (transpose from bf16)
        {
            const int vr = t >> 1, dblk = (t & 1) * 32;
            const bf* vp = g_v + (size_t)(j0 + vr) * HID + h * DHEAD + dblk;
            uint32_t w[16];
            *(uint4*)&w[0]  = *(const uint4*)vp;
            *(uint4*)&w[4]  = *(const uint4*)(vp + 8);
            *(uint4*)&w[8]  = *(const uint4*)(vp + 16);
            *(uint4*)&w[12] = *(const uint4*)(vp + 24);
#pragma unroll
            for (int i = 0; i < 16; i++) {
                __nv_bfloat162 p = *(__nv_bfloat162*)&w[i];
                Vt[(dblk + 2*i + 0) * PSTR + vr] = p.x;
                Vt[(dblk + 2*i + 1) * PSTR + vr] = p.y;
            }
        }
        const int dmin = 1024 + i0 - j0 - 127;
        // stage bS = pk band (raw copy)
        {
            const bf* bp = g_pk + (size_t)(dmin + brow) * HID + h * DHEAD;
            bf* d = &bS[brow * QSTR];
#pragma unroll
            for (int f = 0; f < 8; f++)
                *(uint4*)(d + f * 8) = *(const uint4*)(bp + f * 8);
        }
        __syncthreads();

        float S[4][4][4];
#pragma unroll
        for (int i = 0; i < 4; i++)
#pragma unroll
            for (int j = 0; j < 4; j++)
#pragma unroll
                for (int e = 0; e < 4; e++) S[i][j][e] = 0.0f;

#pragma unroll
        for (int kk = 0; kk < 4; kk++) {
            uint32_t af[4][4], bf2[4][2];
#pragma unroll
            for (int tm = 0; tm < 4; tm++)
                ldsm4(af[tm], qSb + aoffQ + tm * 16 * QSTR * 2 + kk * 32);
#pragma unroll
            for (int tnp = 0; tnp < 2; tnp++) {
                uint32_t bb[4];
                ldsm4(bb, kSb + boffQ + tnp * 16 * QSTR * 2 + kk * 32);
                bf2[2*tnp][0] = bb[0]; bf2[2*tnp][1] = bb[1];
                bf2[2*tnp+1][0] = bb[2]; bf2[2*tnp+1][1] = bb[3];
            }
#pragma unroll
            for (int tm = 0; tm < 4; tm++)
#pragma unroll
                for (int tn = 0; tn < 4; tn++) mma16(S[tm][tn], af[tm], bf2[tn]);
        }

        for (int pass = 0; pass < 2; pass++) {
            if (pass == 1) {
                const bf* bp = g_pq + (size_t)(dmin + brow) * HID + h * DHEAD;
                bf* d = &bS[brow * QSTR];
#pragma unroll
                for (int f = 0; f < 8; f++)
                    *(uint4*)(d + f * 8) = *(const uint4*)(bp + f * 8);
                __syncthreads();
            }
            const uint32_t Xb = (pass == 0) ? qSb : kSb;
            for (int bh = 0; bh < 2; bh++) {
                float Ga[4][4][4];
#pragma unroll
                for (int i = 0; i < 4; i++)
#pragma unroll
                    for (int j = 0; j < 4; j++)
#pragma unroll
                        for (int e = 0; e < 4; e++) Ga[i][j][e] = 0.0f;
#pragma unroll
                for (int kk = 0; kk < 4; kk++) {
                    uint32_t af[4][4], bf2[4][2];
#pragma unroll
                    for (int tm = 0; tm < 4; tm++)
                        ldsm4(af[tm], Xb + aoffQ + tm * 16 * QSTR * 2 + kk * 32);
#pragma unroll
                    for (int tnp = 0; tnp < 2; tnp++) {
                        uint32_t bb[4];
                        ldsm4(bb, bSb + boffQ + (bh * 128 + tnp * 16) * QSTR * 2 + kk * 32);
                        bf2[2*tnp][0] = bb[0]; bf2[2*tnp][1] = bb[1];
                        bf2[2*tnp+1][0] = bb[2]; bf2[2*tnp+1][1] = bb[3];
                    }
#pragma unroll
                    for (int tm = 0; tm < 4; tm++)
#pragma unroll
                        for (int tn = 0; tn < 4; tn++) mma16(Ga[tm][tn], af[tm], bf2[tn]);
                }
#pragma unroll
                for (int tm = 0; tm < 4; tm++)
#pragma unroll
                    for (int tn = 0; tn < 4; tn++) {
                        const int r = wm * 64 + tm * 16 + g;
                        const int c = wn * 32 + tn * 8 + 2 * qd;
                        *(float2*)&Gs[r * 132 + c] = make_float2(Ga[tm][tn][0], Ga[tm][tn][1]);
                        *(float2*)&Gs[(r + 8) * 132 + c] = make_float2(Ga[tm][tn][2], Ga[tm][tn][3]);
                    }
                __syncthreads();
#pragma unroll
                for (int tm = 0; tm < 4; tm++)
#pragma unroll
                    for (int tn = 0; tn < 4; tn++) {
                        const int il = wm * 64 + tm * 16 + g;
                        const int jl = wn * 32 + tn * 8 + 2 * qd;
                        const int b0v = il - jl + 127 - bh * 128;
                        const int bv[4] = {b0v, b0v - 1, b0v + 8, b0v + 7};
                        int rv[4];
                        if (pass == 0) { rv[0] = il; rv[1] = il; rv[2] = il + 8; rv[3] = il + 8; }
                        else           { rv[0] = jl; rv[1] = jl + 1; rv[2] = jl; rv[3] = jl + 1; }
#pragma unroll
                        for (int e = 0; e < 4; e++)
                            if ((unsigned)bv[e] < 128u)
                                S[tm][tn][e] += Gs[rv[e] * 132 + bv[e]];
                    }
                __syncthreads();
            }
        }

#pragma unroll
        for (int tm = 0; tm < 4; tm++) {
            float s0 = 0.0f, s1 = 0.0f;
            const int r = wm * 64 + tm * 16 + g;
            const int c = wn * 32 + 2 * qd;
#pragma unroll
            for (int tn = 0; tn < 4; tn++) {
                float e0 = __expf(S[tm][tn][0] * inv);
                float e1 = __expf(S[tm][tn][1] * inv);
                float e2 = __expf(S[tm][tn][2] * inv);
                float e3 = __expf(S[tm][tn][3] * inv);
                s0 += e0 + e1; s1 += e2 + e3;
                *(uint32_t*)&Ps[r * PSTR + c + tn * 8] = f2bf2(e0, e1);
                *(uint32_t*)&Ps[(r + 8) * PSTR + c + tn * 8] = f2bf2(e2, e3);
            }
            rs[tm][0] += s0; rs[tm][1] += s1;
        }
        __syncthreads();

#pragma unroll
        for (int kk = 0; kk < 8; kk++) {
            uint32_t af[4][4], bf2[2][2];
#pragma unroll
            for (int tm = 0; tm < 4; tm++)
                ldsm4(af[tm], PsB + aoffP + tm * 16 * PSTR * 2 + kk * 32);
            {
                uint32_t bb[4];
                ldsm4(bb, VtB + boffV + kk * 32);
                bf2[0][0] = bb[0]; bf2[0][1] = bb[1];
                bf2[1][0] = bb[2]; bf2[1][1] = bb[3];
            }
#pragma unroll
            for (int tm = 0; tm < 4; tm++)
#pragma unroll
                for (int tn = 0; tn < 2; tn++) mma16(acc[tm][tn], af[tm], bf2[tn]);
        }
    }

    __syncthreads();
#pragma unroll
    for (int tm = 0; tm < 4; tm++) {
        float s0 = rs[tm][0], s1 = rs[tm][1];
        s0 += __shfl_xor_sync(0xffffffffu, s0, 1);
        s0 += __shfl_xor_sync(0xffffffffu, s0, 2);
        s1 += __shfl_xor_sync(0xffffffffu, s1, 1);
        s1 += __shfl_xor_sync(0xffffffffu, s1, 2);
        if (qd == 0) {
            const int r = wm * 64 + tm * 16 + g;
            red[r * 4 + wn] = s0;
            red[(r + 8) * 4 + wn] = s1;
        }
    }
    __syncthreads();
    if (t < 128) {
        float s = red[t * 4] + red[t * 4 + 1] + red[t * 4 + 2] + red[t * 4 + 3];
        red[t * 4] = 1.0f / s;
    }
    __syncthreads();
#pragma unroll
    for (int tm = 0; tm < 4; tm++) {
        const int rl = wm * 64 + tm * 16 + g;
        const float ri0 = red[rl * 4];
        const float ri1 = red[(rl + 8) * 4];
#pragma unroll
        for (int tn = 0; tn < 2; tn++) {
            const int row = i0 + rl;
            const int col = h * DHEAD + wn * 16 + tn * 8 + 2 * qd;
            *(uint32_t*)&g_ctx[(size_t)row * HID + col] =
                f2bf2(acc[tm][tn][0] * ri0, acc[tm][tn][1] * ri0);
            *(uint32_t*)&g_ctx[(size_t)(row + 8) * HID + col] =
                f2bf2(acc[tm][tn][2] * ri1, acc[tm][tn][3] * ri1);
        }
    }
}

// ===== residual + split-K reduce + bias + LayerNorm =====
__global__ __launch_bounds__(256)
void ln_kernel(const float* __restrict__ hs, const float* __restrict__ bo,
               const float* __restrict__ gg, const float* __restrict__ bb,
               float* __restrict__ out)
{
    const int row = blockIdx.x, t = threadIdx.x;
    __shared__ float red[8];
    float4 p0 = *(const float4*)(g_part0 + (size_t)row * HID + t * 4);
    float4 p1 = *(const float4*)(g_part1 + (size_t)row * HID + t * 4);
    float4 bv = *(const float4*)(bo + t * 4);
    float4 hv = *(const float4*)(hs + (size_t)row * HID + t * 4);
    float x0 = p0.x + p1.x + bv.x + hv.x;
    float x1 = p0.y + p1.y + bv.y + hv.y;
    float x2 = p0.z + p1.z + bv.z + hv.z;
    float x3 = p0.w + p1.w + bv.w + hv.w;
    float s = x0+x1+x2+x3;
#pragma unroll
    for (int o = 16; o > 0; o >>= 1) s += __shfl_xor_sync(0xffffffffu, s, o);
    if ((t & 31) == 0) red[t >> 5] = s;
    __syncthreads();
    float mu = (red[0]+red[1]+red[2]+red[3]+red[4]+red[5]+red[6]+red[7]) * (1.0f/1024.0f);
    float d0 = x0-mu, d1 = x1-mu, d2 = x2-mu, d3 = x3-mu;
    float sq = d0*d0 + d1*d1 + d2*d2 + d3*d3;
#pragma unroll
    for (int o = 16; o > 0; o >>= 1) sq += __shfl_xor_sync(0xffffffffu, sq, o);
    __syncthreads();
    if ((t & 31) == 0) red[t >> 5] = sq;
    __syncthreads();
    float var = (red[0]+red[1]+red[2]+red[3]+red[4]+red[5]+red[6]+red[7]) * (1.0f/1024.0f);
    float rstd = rsqrtf(var + 1e-7f);
    float4 g4 = *(const float4*)(gg + t * 4);
    float4 b4 = *(const float4*)(bb + t * 4);
    *(float4*)(out + (size_t)row * HID + t * 4) =
        make_float4(d0*rstd*g4.x + b4.x, d1*rstd*g4.y + b4.y,
                    d2*rstd*g4.z + b4.z, d3*rstd*g4.w + b4.w);
}

extern "C" void kernel_launch(void* const* d_in, const int* in_sizes, int n_in,
                              void* d_out, int out_size)
{
    const float* hs  = (const float*)d_in[0];
    const float* rel = (const float*)d_in[1];
    const float* Wq  = (const float*)d_in[2];  const float* bq  = (const float*)d_in[3];
    const float* Wk  = (const float*)d_in[4];  const float* bk  = (const float*)d_in[5];
    const float* Wv  = (const float*)d_in[6];  const float* bv  = (const float*)d_in[7];
    const float* Wpk = (const float*)d_in[8];  const float* bpk = (const float*)d_in[9];
    const float* Wpq = (const float*)d_in[10]; const float* bpq = (const float*)d_in[11];
    const float* Wo  = (const float*)d_in[12]; const float* bo  = (const float*)d_in[13];
    const float* lng = (const float*)d_in[14]; const float* lnb = (const float*)d_in[15];

    bf *hsb, *relb, *Wqb, *Wkb, *Wvb, *Wpkb, *Wpqb, *qb, *kb, *vb, *pkb, *pqb;
    cudaGetSymbolAddress((void**)&hsb, g_hsb);
    cudaGetSymbolAddress((void**)&relb, g_relb);
    cudaGetSymbolAddress((void**)&Wqb, g_Wqb);
    cudaGetSymbolAddress((void**)&Wkb, g_Wkb);
    cudaGetSymbolAddress((void**)&Wvb, g_Wvb);
    cudaGetSymbolAddress((void**)&Wpkb, g_Wpkb);
    cudaGetSymbolAddress((void**)&Wpqb, g_Wpqb);
    cudaGetSymbolAddress((void**)&qb, g_q);
    cudaGetSymbolAddress((void**)&kb, g_k);
    cudaGetSymbolAddress((void**)&vb, g_v);
    cudaGetSymbolAddress((void**)&pkb, g_pk);
    cudaGetSymbolAddress((void**)&pqb, g_pq);

    const int fused_smem = (128 * QSTR + 128 * QSTR + 256 * QSTR) * 2
                         + 128 * 132 * 4 + 64 * PSTR * 2;
    cudaFuncSetAttribute(attn_fused, cudaFuncAttributeMaxDynamicSharedMemorySize, fused_smem);

    conv_bf16<<<dim3(512, 9), 256>>>(hs, rel, Wq, Wk, Wv, Wpk, Wpq, Wo);
    gemm_proj<<<dim3(8, 8, 3), 256>>>(hsb, Wqb, bq, qb, Wkb, bk, kb, Wvb, bv, vb);
    gemm_proj<<<dim3(8, 16, 2), 256>>>(relb, Wpkb, bpk, pkb, Wpqb, bpq, pqb, Wpqb, bpq, pqb);
    attn_fused<<<dim3(8, 16), 256, fused_smem>>>();
    gemm_wo<<<dim3(8, 8, 2), 256>>>();
    ln_kernel<<<1024, 256>>>(hs, bo, lng, lnb, (float*)d_out);
}

// round 17
// speedup vs baseline: 2.4864x; 1.0803x over previous
#include <cuda_runtime.h>
#include <cuda_bf16.h>
#include <stdint.h>

#define HID   1024
#define NSEQ  1024
#define DHEAD 64

typedef __nv_bfloat16 bf;

__device__ bf g_hsb[NSEQ * HID];
__device__ bf g_relb[2048 * HID];
__device__ bf g_Wqb[HID * HID];
__device__ bf g_Wkb[HID * HID];
__device__ bf g_Wvb[HID * HID];
__device__ bf g_Wpkb[HID * HID];
__device__ bf g_Wpqb[HID * HID];
__device__ bf g_Wob[HID * HID];
__device__ bf g_q[NSEQ * HID];
__device__ bf g_k[NSEQ * HID];
__device__ bf g_v[NSEQ * HID];
__device__ bf g_pk[2048 * HID];
__device__ bf g_pq[2048 * HID];
__device__ bf g_ctx[NSEQ * HID];
__device__ float g_part0[NSEQ * HID];
__device__ float g_part1[NSEQ * HID];

__device__ __forceinline__ uint32_t f2bf2(float lo, float hi) {
    uint32_t r;
    asm("cvt.rn.bf16x2.f32 %0, %1, %2;" : "=r"(r) : "f"(hi), "f"(lo));
    return r;
}
__device__ __forceinline__ void mma16(float* c, const uint32_t* a, const uint32_t* b) {
    asm volatile(
        "mma.sync.aligned.m16n8k16.row.col.f32.bf16.bf16.f32 "
        "{%0,%1,%2,%3}, {%4,%5,%6,%7}, {%8,%9}, {%0,%1,%2,%3};\n"
        : "+f"(c[0]), "+f"(c[1]), "+f"(c[2]), "+f"(c[3])
        : "r"(a[0]), "r"(a[1]), "r"(a[2]), "r"(a[3]), "r"(b[0]), "r"(b[1]));
}
__device__ __forceinline__ void ldsm4(uint32_t* r, uint32_t addr) {
    asm volatile("ldmatrix.sync.aligned.m8n8.x4.shared.b16 {%0,%1,%2,%3}, [%4];\n"
        : "=r"(r[0]), "=r"(r[1]), "=r"(r[2]), "=r"(r[3]) : "r"(addr));
}
__device__ __forceinline__ uint32_t smem_u32(const void* p) {
    return (uint32_t)__cvta_generic_to_shared(p);
}
__device__ __forceinline__ void cpa16(uint32_t dst, const void* src) {
    asm volatile("cp.async.cg.shared.global [%0], [%1], 16;\n" :: "r"(dst), "l"(src));
}
__device__ __forceinline__ void cpa_commit() {
    asm volatile("cp.async.commit_group;\n" ::: "memory");
}
__device__ __forceinline__ void cpa_wait0() {
    asm volatile("cp.async.wait_group 0;\n" ::: "memory");
}

// ===== prep: fp32 -> bf16 =====
__global__ __launch_bounds__(256)
void conv_bf16(const float* __restrict__ hs, const float* __restrict__ rel,
               const float* __restrict__ Wq, const float* __restrict__ Wk,
               const float* __restrict__ Wv, const float* __restrict__ Wpk,
               const float* __restrict__ Wpq, const float* __restrict__ Wo)
{
    const int y = blockIdx.y;
    const float* src; bf* dst;
    switch (y) {
        case 0: src = hs;            dst = g_hsb;            break;
        case 1: src = rel;           dst = g_relb;           break;
        case 2: src = rel + 1048576; dst = g_relb + 1048576; break;
        case 3: src = Wq;            dst = g_Wqb;            break;
        case 4: src = Wk;            dst = g_Wkb;            break;
        case 5: src = Wv;            dst = g_Wvb;            break;
        case 6: src = Wpk;           dst = g_Wpkb;           break;
        case 7: src = Wpq;           dst = g_Wpqb;           break;
        default: src = Wo;           dst = g_Wob;            break;
    }
    const int idx = (blockIdx.x * 256 + threadIdx.x) * 8;
    float4 a = *(const float4*)(src + idx);
    float4 b = *(const float4*)(src + idx + 4);
    *(uint4*)(dst + idx) = make_uint4(f2bf2(a.x, a.y), f2bf2(a.z, a.w),
                                      f2bf2(b.x, b.y), f2bf2(b.z, b.w));
}

#define ASTRIDE 40

// ===== bf16-in GEMM w/ cp.async: C = A@W^T + bias, bf16 out (R16 proven) ====
__global__ __launch_bounds__(256)
void gemm_proj(const bf* __restrict__ A,
               const bf* __restrict__ W0, const float* __restrict__ b0, bf* __restrict__ C0,
               const bf* __restrict__ W1, const float* __restrict__ b1, bf* __restrict__ C1,
               const bf* __restrict__ W2, const float* __restrict__ b2, bf* __restrict__ C2)
{
    __shared__ bf As[2][128 * ASTRIDE];
    __shared__ bf Ws[2][128 * ASTRIDE];

    const int z = blockIdx.z;
    const bf*    W    = (z == 0) ? W0 : ((z == 1) ? W1 : W2);
    const float* bias = (z == 0) ? b0 : ((z == 1) ? b1 : b2);
    bf*          C    = (z == 0) ? C0 : ((z == 1) ? C1 : C2);

    const int m0 = blockIdx.y * 128, n0 = blockIdx.x * 128;
    const int t = threadIdx.x, lane = t & 31, warp = t >> 5;
    const int g = lane >> 2, qd = lane & 3;
    const int wm = warp >> 2, wn = warp & 3;
    const int lr7 = lane & 7;

    const uint32_t aoff = ((uint32_t)((wm * 64 + lr7 + ((lane >> 3) & 1) * 8) * ASTRIDE
                          + (lane >> 4) * 8)) * 2;
    const uint32_t boff = ((uint32_t)((wn * 32 + lr7 + (lane >> 4) * 8) * ASTRIDE
                          + ((lane >> 3) & 1) * 8)) * 2;
    const uint32_t asb = smem_u32(As[0]);
    const uint32_t wsb = smem_u32(Ws[0]);
    const uint32_t bufstep = 128 * ASTRIDE * 2;

    const int lrow = t >> 1, lk = (t & 1) * 16;
    const bf* Ap = A + (size_t)(m0 + lrow) * HID + lk;
    const bf* Wp = W + (size_t)(n0 + lrow) * HID + lk;
    const uint32_t dA = asb + (uint32_t)(lrow * ASTRIDE + lk) * 2;
    const uint32_t dW = wsb + (uint32_t)(lrow * ASTRIDE + lk) * 2;

    cpa16(dA, Ap);       cpa16(dA + 16, Ap + 8);
    cpa16(dW, Wp);       cpa16(dW + 16, Wp + 8);
    cpa_commit(); cpa_wait0();
    __syncthreads();

    float acc[4][4][4];
#pragma unroll
    for (int i = 0; i < 4; i++)
#pragma unroll
        for (int j = 0; j < 4; j++)
#pragma unroll
            for (int e = 0; e < 4; e++) acc[i][j][e] = 0.0f;

    for (int kt = 0; kt < 32; kt++) {
        const int cur = kt & 1;
        const bool more = (kt + 1 < 32);
        if (more) {
            const int nx = cur ^ 1;
            cpa16(dA + nx * bufstep, Ap + (kt + 1) * 32);
            cpa16(dA + nx * bufstep + 16, Ap + (kt + 1) * 32 + 8);
            cpa16(dW + nx * bufstep, Wp + (kt + 1) * 32);
            cpa16(dW + nx * bufstep + 16, Wp + (kt + 1) * 32 + 8);
            cpa_commit();
        }
        const uint32_t Abase = asb + cur * bufstep + aoff;
        const uint32_t Bbase = wsb + cur * bufstep + boff;
#pragma unroll
        for (int kk = 0; kk < 2; kk++) {
            uint32_t af[4][4], bf2[4][2];
#pragma unroll
            for (int tm = 0; tm < 4; tm++)
                ldsm4(af[tm], Abase + tm * 16 * ASTRIDE * 2 + kk * 32);
#pragma unroll
            for (int tnp = 0; tnp < 2; tnp++) {
                uint32_t bb[4];
                ldsm4(bb, Bbase + tnp * 16 * ASTRIDE * 2 + kk * 32);
                bf2[2*tnp][0] = bb[0]; bf2[2*tnp][1] = bb[1];
                bf2[2*tnp+1][0] = bb[2]; bf2[2*tnp+1][1] = bb[3];
            }
#pragma unroll
            for (int tm = 0; tm < 4; tm++)
#pragma unroll
                for (int tn = 0; tn < 4; tn++) mma16(acc[tm][tn], af[tm], bf2[tn]);
        }
        if (more) {
            cpa_wait0();
            __syncthreads();
        }
    }

#pragma unroll
    for (int tm = 0; tm < 4; tm++)
#pragma unroll
        for (int tn = 0; tn < 4; tn++) {
            const int row = m0 + wm * 64 + tm * 16 + g;
            const int col = n0 + wn * 32 + tn * 8 + 2 * qd;
            const float bv0 = bias[col], bv1 = bias[col + 1];
            *(uint32_t*)&C[(size_t)row * HID + col] =
                f2bf2(acc[tm][tn][0] + bv0, acc[tm][tn][1] + bv1);
            *(uint32_t*)&C[(size_t)(row + 8) * HID + col] =
                f2bf2(acc[tm][tn][2] + bv0, acc[tm][tn][3] + bv1);
        }
}

// ===== Wo split-K (R16 proven) =====
__global__ __launch_bounds__(256)
void gemm_wo()
{
    __shared__ bf As[2][128 * ASTRIDE];
    __shared__ bf Ws[2][128 * ASTRIDE];

    const int z = blockIdx.z;
    float* C = (z == 0) ? g_part0 : g_part1;
    const int koff = z * 512;

    const int m0 = blockIdx.y * 128, n0 = blockIdx.x * 128;
    const int t = threadIdx.x, lane = t & 31, warp = t >> 5;
    const int g = lane >> 2, qd = lane & 3;
    const int wm = warp >> 2, wn = warp & 3;
    const int lr7 = lane & 7;

    const uint32_t aoff = ((uint32_t)((wm * 64 + lr7 + ((lane >> 3) & 1) * 8) * ASTRIDE
                          + (lane >> 4) * 8)) * 2;
    const uint32_t boff = ((uint32_t)((wn * 32 + lr7 + (lane >> 4) * 8) * ASTRIDE
                          + ((lane >> 3) & 1) * 8)) * 2;
    const uint32_t asb = smem_u32(As[0]);
    const uint32_t wsb = smem_u32(Ws[0]);
    const uint32_t bufstep = 128 * ASTRIDE * 2;

    const int lrow = t >> 1, lk = (t & 1) * 16;
    const bf* Ap = g_ctx + (size_t)(m0 + lrow) * HID + koff + lk;
    const bf* Wp = g_Wob + (size_t)(n0 + lrow) * HID + koff + lk;
    const uint32_t dA = asb + (uint32_t)(lrow * ASTRIDE + lk) * 2;
    const uint32_t dW = wsb + (uint32_t)(lrow * ASTRIDE + lk) * 2;

    cpa16(dA, Ap);       cpa16(dA + 16, Ap + 8);
    cpa16(dW, Wp);       cpa16(dW + 16, Wp + 8);
    cpa_commit(); cpa_wait0();
    __syncthreads();

    float acc[4][4][4];
#pragma unroll
    for (int i = 0; i < 4; i++)
#pragma unroll
        for (int j = 0; j < 4; j++)
#pragma unroll
            for (int e = 0; e < 4; e++) acc[i][j][e] = 0.0f;

    for (int kt = 0; kt < 16; kt++) {
        const int cur = kt & 1;
        const bool more = (kt + 1 < 16);
        if (more) {
            const int nx = cur ^ 1;
            cpa16(dA + nx * bufstep, Ap + (kt + 1) * 32);
            cpa16(dA + nx * bufstep + 16, Ap + (kt + 1) * 32 + 8);
            cpa16(dW + nx * bufstep, Wp + (kt + 1) * 32);
            cpa16(dW + nx * bufstep + 16, Wp + (kt + 1) * 32 + 8);
            cpa_commit();
        }
        const uint32_t Abase = asb + cur * bufstep + aoff;
        const uint32_t Bbase = wsb + cur * bufstep + boff;
#pragma unroll
        for (int kk = 0; kk < 2; kk++) {
            uint32_t af[4][4], bf2[4][2];
#pragma unroll
            for (int tm = 0; tm < 4; tm++)
                ldsm4(af[tm], Abase + tm * 16 * ASTRIDE * 2 + kk * 32);
#pragma unroll
            for (int tnp = 0; tnp < 2; tnp++) {
                uint32_t bb[4];
                ldsm4(bb, Bbase + tnp * 16 * ASTRIDE * 2 + kk * 32);
                bf2[2*tnp][0] = bb[0]; bf2[2*tnp][1] = bb[1];
                bf2[2*tnp+1][0] = bb[2]; bf2[2*tnp+1][1] = bb[3];
            }
#pragma unroll
            for (int tm = 0; tm < 4; tm++)
#pragma unroll
                for (int tn = 0; tn < 4; tn++) mma16(acc[tm][tn], af[tm], bf2[tn]);
        }
        if (more) {
            cpa_wait0();
            __syncthreads();
        }
    }

#pragma unroll
    for (int tm = 0; tm < 4; tm++)
#pragma unroll
        for (int tn = 0; tn < 4; tn++) {
            const int row = m0 + wm * 64 + tm * 16 + g;
            const int col = n0 + wn * 32 + tn * 8 + 2 * qd;
            *(float2*)&C[(size_t)row * HID + col] =
                make_float2(acc[tm][tn][0], acc[tm][tn][1]);
            *(float2*)&C[(size_t)(row + 8) * HID + col] =
                make_float2(acc[tm][tn][2], acc[tm][tn][3]);
        }
}

#define QSTR 72
#define PSTR 136

// ===== fused attention with shift-at-store band handling =====
__global__ __launch_bounds__(256, 1)
void attn_fused()
{
    extern __shared__ char smraw[];
    bf*    qS = (bf*)smraw;
    bf*    kS = qS + 128 * QSTR;
    bf*    bS = kS + 128 * QSTR;
    float* Gs = (float*)(bS + 256 * QSTR);   // shifted G [128][132]
    bf*    Ps = (bf*)Gs;
    bf*    Vt = (bf*)(Gs + 128 * 132);
    float* red = (float*)kS;

    const int h = blockIdx.y, i0 = blockIdx.x * 128;
    const int t = threadIdx.x, lane = t & 31, warp = t >> 5;
    const int g = lane >> 2, qd = lane & 3;
    const int wm = warp >> 2, wn = warp & 3;
    const int lr7 = lane & 7;

    const uint32_t aoffQ = ((uint32_t)((wm*64 + lr7 + ((lane>>3)&1)*8) * QSTR + (lane>>4)*8)) * 2;
    const uint32_t boffQ = ((uint32_t)((wn*32 + lr7 + (lane>>4)*8) * QSTR + ((lane>>3)&1)*8)) * 2;
    const uint32_t aoffP = ((uint32_t)((wm*64 + lr7 + ((lane>>3)&1)*8) * PSTR + (lane>>4)*8)) * 2;
    const uint32_t boffV = ((uint32_t)((wn*16 + lr7 + (lane>>4)*8) * PSTR + ((lane>>3)&1)*8)) * 2;
    const uint32_t qSb = smem_u32(qS), kSb = smem_u32(kS), bSb = smem_u32(bS);
    const uint32_t PsB = smem_u32(Ps), VtB = smem_u32(Vt);

    // stage qS once (cp.async)
    const int lrow = t >> 1, dh = (t & 1) * 32;
    {
        const bf* qp = g_q + (size_t)(i0 + lrow) * HID + h * DHEAD + dh;
        const uint32_t dq = qSb + (uint32_t)(lrow * QSTR + dh) * 2;
        cpa16(dq, qp); cpa16(dq + 16, qp + 8);
        cpa16(dq + 32, qp + 16); cpa16(dq + 48, qp + 24);
        cpa_commit();
    }

    float acc[4][2][4];
#pragma unroll
    for (int i = 0; i < 4; i++)
#pragma unroll
        for (int j = 0; j < 2; j++)
#pragma unroll
            for (int e = 0; e < 4; e++) acc[i][j][e] = 0.0f;
    float rs[4][2];
#pragma unroll
    for (int i = 0; i < 4; i++) { rs[i][0] = 0.0f; rs[i][1] = 0.0f; }

    const int brow = (t < 255) ? t : 254;
    const float inv = 0.07216878364870322992f;
    const uint32_t dk = kSb + (uint32_t)(lrow * QSTR + dh) * 2;
    const uint32_t db = bSb + (uint32_t)(brow * QSTR) * 2;

    for (int j0 = 0; j0 < NSEQ; j0 += 128) {
        __syncthreads();
        // stage kS (cp.async)
        {
            const bf* kp = g_k + (size_t)(j0 + lrow) * HID + h * DHEAD + dh;
            cpa16(dk, kp); cpa16(dk + 16, kp + 8);
            cpa16(dk + 32, kp + 16); cpa16(dk + 48, kp + 24);
        }
        // stage bS = pk band (cp.async)
        const int dmin = 1024 + i0 - j0 - 127;
        {
            const bf* bp = g_pk + (size_t)(dmin + brow) * HID + h * DHEAD;
#pragma unroll
            for (int f = 0; f < 8; f++) cpa16(db + f * 16, bp + f * 8);
        }
        cpa_commit();
        // stage Vt[d][j] (manual transpose)
        {
            const int vr = t >> 1, dblk = (t & 1) * 32;
            const bf* vp = g_v + (size_t)(j0 + vr) * HID + h * DHEAD + dblk;
            uint32_t w[16];
            *(uint4*)&w[0]  = *(const uint4*)vp;
            *(uint4*)&w[4]  = *(const uint4*)(vp + 8);
            *(uint4*)&w[8]  = *(const uint4*)(vp + 16);
            *(uint4*)&w[12] = *(const uint4*)(vp + 24);
#pragma unroll
            for (int i = 0; i < 16; i++) {
                __nv_bfloat162 p = *(__nv_bfloat162*)&w[i];
                Vt[(dblk + 2*i + 0) * PSTR + vr] = p.x;
                Vt[(dblk + 2*i + 1) * PSTR + vr] = p.y;
            }
        }
        cpa_wait0();
        __syncthreads();

        float S[4][4][4];
#pragma unroll
        for (int i = 0; i < 4; i++)
#pragma unroll
            for (int j = 0; j < 4; j++)
#pragma unroll
                for (int e = 0; e < 4; e++) S[i][j][e] = 0.0f;

        // QK
#pragma unroll
        for (int kk = 0; kk < 4; kk++) {
            uint32_t af[4][4], bf2[4][2];
#pragma unroll
            for (int tm = 0; tm < 4; tm++)
                ldsm4(af[tm], qSb + aoffQ + tm * 16 * QSTR * 2 + kk * 32);
#pragma unroll
            for (int tnp = 0; tnp < 2; tnp++) {
                uint32_t bb[4];
                ldsm4(bb, kSb + boffQ + tnp * 16 * QSTR * 2 + kk * 32);
                bf2[2*tnp][0] = bb[0]; bf2[2*tnp][1] = bb[1];
                bf2[2*tnp+1][0] = bb[2]; bf2[2*tnp+1][1] = bb[3];
            }
#pragma unroll
            for (int tm = 0; tm < 4; tm++)
#pragma unroll
                for (int tn = 0; tn < 4; tn++) mma16(S[tm][tn], af[tm], bf2[tn]);
        }

        // band passes with shift-at-store
        for (int pass = 0; pass < 2; pass++) {
            if (pass == 1) {
                // restage bS = pq (gather sync below covered prior reads)
                const bf* bp = g_pq + (size_t)(dmin + brow) * HID + h * DHEAD;
#pragma unroll
                for (int f = 0; f < 8; f++) cpa16(db + f * 16, bp + f * 8);
                cpa_commit(); cpa_wait0();
                __syncthreads();
            }
            const uint32_t Xb = (pass == 0) ? qSb : kSb;
            for (int bh = 0; bh < 2; bh++) {
                float Ga[4][4][4];
#pragma unroll
                for (int i = 0; i < 4; i++)
#pragma unroll
                    for (int j = 0; j < 4; j++)
#pragma unroll
                        for (int e = 0; e < 4; e++) Ga[i][j][e] = 0.0f;
#pragma unroll
                for (int kk = 0; kk < 4; kk++) {
                    uint32_t af[4][4], bf2[4][2];
#pragma unroll
                    for (int tm = 0; tm < 4; tm++)
                        ldsm4(af[tm], Xb + aoffQ + tm * 16 * QSTR * 2 + kk * 32);
#pragma unroll
                    for (int tnp = 0; tnp < 2; tnp++) {
                        uint32_t bb[4];
                        ldsm4(bb, bSb + boffQ + (bh * 128 + tnp * 16) * QSTR * 2 + kk * 32);
                        bf2[2*tnp][0] = bb[0]; bf2[2*tnp][1] = bb[1];
                        bf2[2*tnp+1][0] = bb[2]; bf2[2*tnp+1][1] = bb[3];
                    }
#pragma unroll
                    for (int tm = 0; tm < 4; tm++)
#pragma unroll
                        for (int tn = 0; tn < 4; tn++) mma16(Ga[tm][tn], af[tm], bf2[tn]);
                }
                // shift-at-store: place each value at its (i, j) destination
                if (pass == 0) {
                    // G1(r,c): j = r + 127 - bh*128 - c
#pragma unroll
                    for (int tm = 0; tm < 4; tm++)
#pragma unroll
                        for (int tn = 0; tn < 4; tn++) {
                            const int r0 = wm * 64 + tm * 16 + g;
                            const int c0 = wn * 32 + tn * 8 + 2 * qd;
                            const int jj = r0 + 127 - bh * 128 - c0;
                            if ((unsigned)jj < 128u)       Gs[r0 * 132 + jj]           = Ga[tm][tn][0];
                            if ((unsigned)(jj - 1) < 128u) Gs[r0 * 132 + jj - 1]       = Ga[tm][tn][1];
                            if ((unsigned)(jj + 8) < 128u) Gs[(r0 + 8) * 132 + jj + 8] = Ga[tm][tn][2];
                            if ((unsigned)(jj + 7) < 128u) Gs[(r0 + 8) * 132 + jj + 7] = Ga[tm][tn][3];
                        }
                } else {
                    // G2(r,c): i = r + bh*128 + c - 127, j = r
#pragma unroll
                    for (int tm = 0; tm < 4; tm++)
#pragma unroll
                        for (int tn = 0; tn < 4; tn++) {
                            const int r0 = wm * 64 + tm * 16 + g;
                            const int c0 = wn * 32 + tn * 8 + 2 * qd;
                            const int ii = r0 + bh * 128 + c0 - 127;
                            if ((unsigned)ii < 128u)       Gs[ii * 132 + r0]           = Ga[tm][tn][0];
                            if ((unsigned)(ii + 1) < 128u) Gs[(ii + 1) * 132 + r0]     = Ga[tm][tn][1];
                            if ((unsigned)(ii + 8) < 128u) Gs[(ii + 8) * 132 + r0 + 8] = Ga[tm][tn][2];
                            if ((unsigned)(ii + 9) < 128u) Gs[(ii + 9) * 132 + r0 + 8] = Ga[tm][tn][3];
                        }
                }
                // no sync between bh rounds: disjoint writes
            }
            __syncthreads();
            // aligned vector gather: S += Gs at own coords
#pragma unroll
            for (int tm = 0; tm < 4; tm++)
#pragma unroll
                for (int tn = 0; tn < 4; tn++) {
                    const int il = wm * 64 + tm * 16 + g;
                    const int jl = wn * 32 + tn * 8 + 2 * qd;
                    float2 v0 = *(const float2*)&Gs[il * 132 + jl];
                    float2 v1 = *(const float2*)&Gs[(il + 8) * 132 + jl];
                    S[tm][tn][0] += v0.x; S[tm][tn][1] += v0.y;
                    S[tm][tn][2] += v1.x; S[tm][tn][3] += v1.y;
                }
            __syncthreads();
        }

        // exp -> Ps (bf16) + rowsum
#pragma unroll
        for (int tm = 0; tm < 4; tm++) {
            float s0 = 0.0f, s1 = 0.0f;
            const int r = wm * 64 + tm * 16 + g;
            const int c = wn * 32 + 2 * qd;
#pragma unroll
            for (int tn = 0; tn < 4; tn++) {
                float e0 = __expf(S[tm][tn][0] * inv);
                float e1 = __expf(S[tm][tn][1] * inv);
                float e2 = __expf(S[tm][tn][2] * inv);
                float e3 = __expf(S[tm][tn][3] * inv);
                s0 += e0 + e1; s1 += e2 + e3;
                *(uint32_t*)&Ps[r * PSTR + c + tn * 8] = f2bf2(e0, e1);
                *(uint32_t*)&Ps[(r + 8) * PSTR + c + tn * 8] = f2bf2(e2, e3);
            }
            rs[tm][0] += s0; rs[tm][1] += s1;
        }
        __syncthreads();

        // AV
#pragma unroll
        for (int kk = 0; kk < 8; kk++) {
            uint32_t af[4][4], bf2[2][2];
#pragma unroll
            for (int tm = 0; tm < 4; tm++)
                ldsm4(af[tm], PsB + aoffP + tm * 16 * PSTR * 2 + kk * 32);
            {
                uint32_t bb[4];
                ldsm4(bb, VtB + boffV + kk * 32);
                bf2[0][0] = bb[0]; bf2[0][1] = bb[1];
                bf2[1][0] = bb[2]; bf2[1][1] = bb[3];
            }
#pragma unroll
            for (int tm = 0; tm < 4; tm++)
#pragma unroll
                for (int tn = 0; tn < 2; tn++) mma16(acc[tm][tn], af[tm], bf2[tn]);
        }
    }

    __syncthreads();
#pragma unroll
    for (int tm = 0; tm < 4; tm++) {
        float s0 = rs[tm][0], s1 = rs[tm][1];
        s0 += __shfl_xor_sync(0xffffffffu, s0, 1);
        s0 += __shfl_xor_sync(0xffffffffu, s0, 2);
        s1 += __shfl_xor_sync(0xffffffffu, s1, 1);
        s1 += __shfl_xor_sync(0xffffffffu, s1, 2);
        if (qd == 0) {
            const int r = wm * 64 + tm * 16 + g;
            red[r * 4 + wn] = s0;
            red[(r + 8) * 4 + wn] = s1;
        }
    }
    __syncthreads();
    if (t < 128) {
        float s = red[t * 4] + red[t * 4 + 1] + red[t * 4 + 2] + red[t * 4 + 3];
        red[t * 4] = 1.0f / s;
    }
    __syncthreads();
#pragma unroll
    for (int tm = 0; tm < 4; tm++) {
        const int rl = wm * 64 + tm * 16 + g;
        const float ri0 = red[rl * 4];
        const float ri1 = red[(rl + 8) * 4];
#pragma unroll
        for (int tn = 0; tn < 2; tn++) {
            const int row = i0 + rl;
            const int col = h * DHEAD + wn * 16 + tn * 8 + 2 * qd;
            *(uint32_t*)&g_ctx[(size_t)row * HID + col] =
                f2bf2(acc[tm][tn][0] * ri0, acc[tm][tn][1] * ri0);
            *(uint32_t*)&g_ctx[(size_t)(row + 8) * HID + col] =
                f2bf2(acc[tm][tn][2] * ri1, acc[tm][tn][3] * ri1);
        }
    }
}

// ===== residual + split-K reduce + bias + LayerNorm =====
__global__ __launch_bounds__(256)
void ln_kernel(const float* __restrict__ hs, const float* __restrict__ bo,
               const float* __restrict__ gg, const float* __restrict__ bb,
               float* __restrict__ out)
{
    const int row = blockIdx.x, t = threadIdx.x;
    __shared__ float red[8];
    float4 p0 = *(const float4*)(g_part0 + (size_t)row * HID + t * 4);
    float4 p1 = *(const float4*)(g_part1 + (size_t)row * HID + t * 4);
    float4 bv = *(const float4*)(bo + t * 4);
    float4 hv = *(const float4*)(hs + (size_t)row * HID + t * 4);
    float x0 = p0.x + p1.x + bv.x + hv.x;
    float x1 = p0.y + p1.y + bv.y + hv.y;
    float x2 = p0.z + p1.z + bv.z + hv.z;
    float x3 = p0.w + p1.w + bv.w + hv.w;
    float s = x0+x1+x2+x3;
#pragma unroll
    for (int o = 16; o > 0; o >>= 1) s += __shfl_xor_sync(0xffffffffu, s, o);
    if ((t & 31) == 0) red[t >> 5] = s;
    __syncthreads();
    float mu = (red[0]+red[1]+red[2]+red[3]+red[4]+red[5]+red[6]+red[7]) * (1.0f/1024.0f);
    float d0 = x0-mu, d1 = x1-mu, d2 = x2-mu, d3 = x3-mu;
    float sq = d0*d0 + d1*d1 + d2*d2 + d3*d3;
#pragma unroll
    for (int o = 16; o > 0; o >>= 1) sq += __shfl_xor_sync(0xffffffffu, sq, o);
    __syncthreads();
    if ((t & 31) == 0) red[t >> 5] = sq;
    __syncthreads();
    float var = (red[0]+red[1]+red[2]+red[3]+red[4]+red[5]+red[6]+red[7]) * (1.0f/1024.0f);
    float rstd = rsqrtf(var + 1e-7f);
    float4 g4 = *(const float4*)(gg + t * 4);
    float4 b4 = *(const float4*)(bb + t * 4);
    *(float4*)(out + (size_t)row * HID + t * 4) =
        make_float4(d0*rstd*g4.x + b4.x, d1*rstd*g4.y + b4.y,
                    d2*rstd*g4.z + b4.z, d3*rstd*g4.w + b4.w);
}

extern "C" void kernel_launch(void* const* d_in, const int* in_sizes, int n_in,
                              void* d_out, int out_size)
{
    const float* hs  = (const float*)d_in[0];
    const float* rel = (const float*)d_in[1];
    const float* Wq  = (const float*)d_in[2];  const float* bq  = (const float*)d_in[3];
    const float* Wk  = (const float*)d_in[4];  const float* bk  = (const float*)d_in[5];
    const float* Wv  = (const float*)d_in[6];  const float* bv  = (const float*)d_in[7];
    const float* Wpk = (const float*)d_in[8];  const float* bpk = (const float*)d_in[9];
    const float* Wpq = (const float*)d_in[10]; const float* bpq = (const float*)d_in[11];
    const float* Wo  = (const float*)d_in[12]; const float* bo  = (const float*)d_in[13];
    const float* lng = (const float*)d_in[14]; const float* lnb = (const float*)d_in[15];

    bf *hsb, *relb, *Wqb, *Wkb, *Wvb, *Wpkb, *Wpqb, *qb, *kb, *vb, *pkb, *pqb;
    cudaGetSymbolAddress((void**)&hsb, g_hsb);
    cudaGetSymbolAddress((void**)&relb, g_relb);
    cudaGetSymbolAddress((void**)&Wqb, g_Wqb);
    cudaGetSymbolAddress((void**)&Wkb, g_Wkb);
    cudaGetSymbolAddress((void**)&Wvb, g_Wvb);
    cudaGetSymbolAddress((void**)&Wpkb, g_Wpkb);
    cudaGetSymbolAddress((void**)&Wpqb, g_Wpqb);
    cudaGetSymbolAddress((void**)&qb, g_q);
    cudaGetSymbolAddress((void**)&kb, g_k);
    cudaGetSymbolAddress((void**)&vb, g_v);
    cudaGetSymbolAddress((void**)&pkb, g_pk);
    cudaGetSymbolAddress((void**)&pqb, g_pq);

    const int fused_smem = (128 * QSTR + 128 * QSTR + 256 * QSTR) * 2
                         + 128 * 132 * 4 + 64 * PSTR * 2;
    cudaFuncSetAttribute(attn_fused, cudaFuncAttributeMaxDynamicSharedMemorySize, fused_smem);

    conv_bf16<<<dim3(512, 9), 256>>>(hs, rel, Wq, Wk, Wv, Wpk, Wpq, Wo);
    gemm_proj<<<dim3(8, 8, 3), 256>>>(hsb, Wqb, bq, qb, Wkb, bk, kb, Wvb, bv, vb);
    gemm_proj<<<dim3(8, 16, 2), 256>>>(relb, Wpkb, bpk, pkb, Wpqb, bpq, pqb, Wpqb, bpq, pqb);
    attn_fused<<<dim3(8, 16), 256, fused_smem>>>();
    gemm_wo<<<dim3(8, 8, 2), 256>>>();
    ln_kernel<<<1024, 256>>>(hs, bo, lng, lnb, (float*)d_out);
}